// round 1
// baseline (speedup 1.0000x reference)
#include <cuda_runtime.h>
#include <math.h>
#include <stdint.h>

#define N_SRC 16384
#define N_DST 8192
#define KNB 32
#define E_TOT (N_DST*KNB)   // 262144
#define T 16
#define H 64
#define D_INP 16
#define PD 80               // D_INP + H
#define G4 256              // 4*H
#define EB 64               // edges per LSTM block

// ---------------- scratch (static device memory; no allocs) ----------------
__device__ float g_eout[(size_t)E_TOT*H];
__device__ float g_aout[(size_t)E_TOT*H];
__device__ float g_m[(size_t)E_TOT*H];
__device__ float g_a[E_TOT];
__device__ float g_P[N_SRC*H];
__device__ float g_Q[N_DST*H];
__device__ int   g_list[E_TOT];
__device__ int   g_cnt[T];
__device__ int   g_cur[T];

// ---------------- bucketing ----------------
__global__ void zero_cnt_kernel() {
    if (threadIdx.x < T) g_cnt[threadIdx.x] = 0;
}

__global__ void hist_kernel(const int* __restrict__ elen) {
    __shared__ int h[T];
    if (threadIdx.x < T) h[threadIdx.x] = 0;
    __syncthreads();
    int i = blockIdx.x * blockDim.x + threadIdx.x;
    int stride = gridDim.x * blockDim.x;
    for (; i < E_TOT; i += stride) atomicAdd(&h[elen[i] - 1], 1);
    __syncthreads();
    if (threadIdx.x < T) atomicAdd(&g_cnt[threadIdx.x], h[threadIdx.x]);
}

__global__ void scan_kernel() {
    // single thread; longest buckets first (better tail behavior)
    int off = 0;
    for (int l = T - 1; l >= 0; --l) { g_cur[l] = off; off += g_cnt[l]; }
}

__global__ void scatter_kernel(const int* __restrict__ elen) {
    int i = blockIdx.x * blockDim.x + threadIdx.x;
    if (i >= E_TOT) return;
    int l = elen[i] - 1;
    unsigned act = __activemask();
    unsigned mask = __match_any_sync(act, l);
    int lane = threadIdx.x & 31;
    int leader = __ffs(mask) - 1;
    int rank = __popc(mask & ((1u << lane) - 1));
    int base = 0;
    if (lane == leader) base = atomicAdd(&g_cur[l], __popc(mask));
    base = __shfl_sync(mask, base, leader);
    g_list[base + rank] = i;
}

// ---------------- LSTM (the hot kernel) ----------------
// block: 256 threads, 64 edges, one LSTM (blockIdx.y selects e/a).
// smem: Ws[80][256] combined [Wih;Whh] (row p, col j), bias[256],
//       As[64][80] = [x_t | h], t2v params, edge idx/len.
__global__ void __launch_bounds__(256, 2) lstm_kernel(
    const float* __restrict__ ef, const float* __restrict__ et,
    const int*   __restrict__ elen,
    const float* __restrict__ t2v_w,  const float* __restrict__ t2v_b,
    const float* __restrict__ t2v_w0, const float* __restrict__ t2v_b0,
    const float* __restrict__ Wih_e, const float* __restrict__ Whh_e,
    const float* __restrict__ bih_e, const float* __restrict__ bhh_e,
    const float* __restrict__ Wih_a, const float* __restrict__ Whh_a,
    const float* __restrict__ bih_a, const float* __restrict__ bhh_a)
{
    extern __shared__ float sm[];
    float* Ws  = sm;                  // 80*256 = 20480
    float* bs  = Ws + PD*G4;          // 256
    float* As  = bs + G4;             // 64*80 = 5120
    float* tv  = As + EB*PD;          // 16
    int*   sidx = (int*)(tv + 16);    // 64
    int*   slen = sidx + EB;          // 64
    int*   smax = slen + EB;          // 1

    const int tid = threadIdx.x;
    const bool isA = (blockIdx.y != 0);
    const float* Wih = isA ? Wih_a : Wih_e;
    const float* Whh = isA ? Whh_a : Whh_e;
    const float* bih = isA ? bih_a : bih_e;
    const float* bhh = isA ? bhh_a : bhh_e;
    float* gout = isA ? g_aout : g_eout;

    for (int idx = tid; idx < PD*G4; idx += 256) {
        int p = idx >> 8, j = idx & 255;
        Ws[idx] = (p < D_INP) ? Wih[j*D_INP + p] : Whh[j*H + (p - D_INP)];
    }
    if (tid < G4) bs[tid] = bih[tid] + bhh[tid];
    if (tid < 7) { tv[tid] = t2v_w[tid]; tv[7 + tid] = t2v_b[tid]; }
    if (tid == 0) { tv[14] = t2v_w0[0]; tv[15] = t2v_b0[0]; *smax = 0; }
    if (tid < EB) {
        int eg = g_list[blockIdx.x * EB + tid];
        sidx[tid] = eg;
        int l = elen[eg];
        slen[tid] = l;
        atomicMax(smax, l);
    }
    for (int idx = tid; idx < EB*PD; idx += 256) As[idx] = 0.f;
    __syncthreads();

    const int tm = tid >> 5;        // 0..7  (edge group)
    const int tn = tid & 31;        // 0..31 (h-dim pair)
    int lens[8];
    #pragma unroll
    for (int i = 0; i < 8; i++) lens[i] = slen[tm*8 + i];
    const int maxlen = *smax;

    float c[16], hl[16];
    #pragma unroll
    for (int i = 0; i < 16; i++) { c[i] = 0.f; hl[i] = 0.f; }

    for (int t = 0; t < maxlen; ++t) {
        __syncthreads();   // prev-step GEMM reads of x done; prev h writes visible
        // fill x_t = [edge_feats(8) | sin(tau*w+b)(7) | tau*w0+b0]
        #pragma unroll
        for (int s = 0; s < 4; s++) {
            int idx = tid + 256*s;
            int el = idx >> 4, col = idx & 15;
            int eg = sidx[el];
            float v;
            if (col < 8) {
                v = ef[((size_t)eg*T + t)*8 + col];
            } else {
                float tau = et[(size_t)eg*T + t];
                v = (col < 15) ? __sinf(fmaf(tau, tv[col-8], tv[7 + col-8]))
                               : fmaf(tau, tv[14], tv[15]);
            }
            As[el*PD + col] = v;
        }
        __syncthreads();

        // gates[64 edges][256] = As @ Ws + bias ; per-thread 8x8 tile
        // col(j) = (j>>1)*64 + tn*2 + (j&1)  -> j pairs = {i,f,g,o} x 2 hdims
        float acc[8][8];
        #pragma unroll
        for (int i = 0; i < 8; i++) {
            #pragma unroll
            for (int j = 0; j < 8; j++) acc[i][j] = bs[(j>>1)*64 + tn*2 + (j&1)];
        }
        #pragma unroll 2
        for (int p = 0; p < PD; p++) {
            const float* wrow = Ws + p*G4 + tn*2;
            float2 b0 = *(const float2*)(wrow);
            float2 b1 = *(const float2*)(wrow + 64);
            float2 b2 = *(const float2*)(wrow + 128);
            float2 b3 = *(const float2*)(wrow + 192);
            #pragma unroll
            for (int i = 0; i < 8; i++) {
                float a = As[(tm*8 + i)*PD + p];
                acc[i][0] = fmaf(a, b0.x, acc[i][0]);
                acc[i][1] = fmaf(a, b0.y, acc[i][1]);
                acc[i][2] = fmaf(a, b1.x, acc[i][2]);
                acc[i][3] = fmaf(a, b1.y, acc[i][3]);
                acc[i][4] = fmaf(a, b2.x, acc[i][4]);
                acc[i][5] = fmaf(a, b2.y, acc[i][5]);
                acc[i][6] = fmaf(a, b3.x, acc[i][6]);
                acc[i][7] = fmaf(a, b3.y, acc[i][7]);
            }
        }
        __syncthreads();   // all GEMM reads done; safe to overwrite h in As

        // LSTM cell (register-local), write new h into As, latch hlast
        #pragma unroll
        for (int i = 0; i < 8; i++) {
            #pragma unroll
            for (int hs = 0; hs < 2; hs++) {
                int ridx = i*2 + hs;
                float iv = 1.f / (1.f + __expf(-acc[i][0 + hs]));
                float fv = 1.f / (1.f + __expf(-acc[i][2 + hs]));
                float gv = tanhf(acc[i][4 + hs]);
                float ov = 1.f / (1.f + __expf(-acc[i][6 + hs]));
                float cn = fmaf(fv, c[ridx], iv * gv);
                c[ridx] = cn;
                float hh = ov * tanhf(cn);
                As[(tm*8 + i)*PD + D_INP + tn*2 + hs] = hh;
                if (t < lens[i]) hl[ridx] = hh;
            }
        }
    }

    #pragma unroll
    for (int i = 0; i < 8; i++) {
        size_t base = (size_t)sidx[tm*8 + i] * H + tn*2;
        gout[base]     = hl[i*2];
        gout[base + 1] = hl[i*2 + 1];
    }
}

// ---------------- projection precompute: P = nf@W1^T, Q = nf[:8192]@nW1^T ----------------
__global__ void proj_kernel(const float* __restrict__ nf,
                            const float* __restrict__ eW,
                            const float* __restrict__ nW)
{
    __shared__ float Wt[64*64];   // Wt[d*64+j] = W[j*128+d]
    __shared__ float xs[16*64];
    const float* W = blockIdx.y ? nW : eW;
    float* out = blockIdx.y ? g_Q : g_P;
    int nrows = blockIdx.y ? N_DST : N_SRC;
    int r0 = blockIdx.x * 16;
    if (r0 >= nrows) return;
    int tid = threadIdx.x;
    for (int idx = tid; idx < 4096; idx += 256) {
        int d = idx >> 6, j = idx & 63;
        Wt[idx] = W[j*128 + d];
    }
    for (int idx = tid; idx < 16*64; idx += 256) xs[idx] = nf[(size_t)r0*64 + idx];
    __syncthreads();
    for (int o = tid; o < 1024; o += 256) {
        int ri = o >> 6, j = o & 63;
        float s = 0.f;
        #pragma unroll
        for (int d = 0; d < 64; d++) s = fmaf(xs[ri*64 + d], Wt[d*64 + j], s);
        out[(size_t)(r0 + ri)*64 + j] = s;
    }
}

// ---------------- edge epilogue: m = relu(P[src] + e_out@W2^T + b), a = lrelu(a_out@attn) ----------------
__global__ void __launch_bounds__(256) edgem_kernel(
    const float* __restrict__ eW, const float* __restrict__ eb,
    const float* __restrict__ attn, const int* __restrict__ esrc)
{
    __shared__ float W2t[64*64];   // [d][j] = eW[j*128+64+d]
    __shared__ float eo[64*64];    // e_out tile [e][d]
    __shared__ float att[64];
    __shared__ float bsh[64];
    int tid = threadIdx.x;
    size_t e0 = (size_t)blockIdx.x * 64;
    for (int idx = tid; idx < 4096; idx += 256) {
        int d = idx >> 6, j = idx & 63;
        W2t[idx] = eW[j*128 + 64 + d];
    }
    if (tid < 64) { att[tid] = attn[tid]; bsh[tid] = eb[tid]; }
    for (int idx = tid; idx < 4096; idx += 256) eo[idx] = g_eout[e0*64 + idx];
    __syncthreads();

    int tm = tid >> 5, tn = tid & 31;
    float acc[8][2];
    #pragma unroll
    for (int i = 0; i < 8; i++) { acc[i][0] = bsh[tn*2]; acc[i][1] = bsh[tn*2 + 1]; }
    #pragma unroll 4
    for (int d = 0; d < 64; d++) {
        float2 w = *(const float2*)(W2t + d*64 + tn*2);
        #pragma unroll
        for (int i = 0; i < 8; i++) {
            float a = eo[(tm*8 + i)*64 + d];
            acc[i][0] = fmaf(a, w.x, acc[i][0]);
            acc[i][1] = fmaf(a, w.y, acc[i][1]);
        }
    }
    #pragma unroll
    for (int i = 0; i < 8; i++) {
        size_t e = e0 + tm*8 + i;
        int src = esrc[e];
        float2 pv = *(const float2*)(g_P + (size_t)src*64 + tn*2);
        float m0 = fmaxf(acc[i][0] + pv.x, 0.f);
        float m1 = fmaxf(acc[i][1] + pv.y, 0.f);
        *(float2*)(g_m + e*64 + tn*2) = make_float2(m0, m1);
    }
    if (tid < 64) {
        size_t e = e0 + tid;
        const float4* ar = (const float4*)(g_aout + e*64);
        float s = 0.f;
        #pragma unroll
        for (int d = 0; d < 16; d++) {
            float4 v = ar[d];
            s += v.x*att[d*4] + v.y*att[d*4+1] + v.z*att[d*4+2] + v.w*att[d*4+3];
        }
        g_a[e] = (s > 0.f) ? s : 0.01f*s;
    }
}

// ---------------- per-dst: sparsemax + aggregate + final MLP ----------------
__global__ void __launch_bounds__(256) dst_kernel(
    const float* __restrict__ nW, const float* __restrict__ nb,
    float* __restrict__ out)
{
    __shared__ float nW2t[64*64];   // [d][j] = nW[j*128+64+d]
    __shared__ float nbs[64];
    __shared__ float hns[8][64];
    int tid = threadIdx.x;
    for (int idx = tid; idx < 4096; idx += 256) {
        int d = idx >> 6, j = idx & 63;
        nW2t[idx] = nW[j*128 + 64 + d];
    }
    if (tid < 64) nbs[tid] = nb[tid];
    __syncthreads();

    int w = tid >> 5, lane = tid & 31;
    int dst = blockIdx.x * 8 + w;
    const unsigned FULL = 0xffffffffu;

    float av = g_a[(size_t)dst*KNB + lane];
    float mx = av;
    #pragma unroll
    for (int o = 16; o > 0; o >>= 1) mx = fmaxf(mx, __shfl_xor_sync(FULL, mx, o));
    float z = av - mx;

    // bitonic sort, descending across lanes
    float v = z;
    #pragma unroll
    for (int k = 2; k <= 32; k <<= 1) {
        #pragma unroll
        for (int j = k >> 1; j > 0; j >>= 1) {
            float o = __shfl_xor_sync(FULL, v, j);
            bool lower = (lane & j) == 0;
            bool asc = (lane & k) != 0;
            v = (lower == asc) ? fminf(v, o) : fmaxf(v, o);
        }
    }
    // inclusive cumsum of sorted values
    float cs = v;
    #pragma unroll
    for (int o = 1; o < 32; o <<= 1) {
        float t = __shfl_up_sync(FULL, cs, o);
        if (lane >= o) cs += t;
    }
    float r = (float)(lane + 1);
    bool gt = (1.f + r*v) > cs;
    float kk = gt ? r : 0.f;
    float sz = gt ? v : 0.f;
    #pragma unroll
    for (int o = 16; o > 0; o >>= 1) {
        kk = fmaxf(kk, __shfl_xor_sync(FULL, kk, o));
        sz += __shfl_xor_sync(FULL, sz, o);
    }
    float tau = (sz - 1.f) / kk;
    float alpha = fmaxf(z - tau, 0.f);

    // h_neigh = sum_k alpha_k * m[dst*K+k]; lane holds dims 2*lane, 2*lane+1
    float hn0 = 0.f, hn1 = 0.f;
    #pragma unroll
    for (int k2 = 0; k2 < 32; k2++) {
        float al = __shfl_sync(FULL, alpha, k2);
        if (al > 0.f) {
            const float2 mv = *(const float2*)(g_m + ((size_t)dst*KNB + k2)*64 + lane*2);
            hn0 = fmaf(al, mv.x, hn0);
            hn1 = fmaf(al, mv.y, hn1);
        }
    }
    hns[w][lane*2]     = hn0;
    hns[w][lane*2 + 1] = hn1;
    __syncwarp();

    float o0 = nbs[lane*2]     + g_Q[(size_t)dst*64 + lane*2];
    float o1 = nbs[lane*2 + 1] + g_Q[(size_t)dst*64 + lane*2 + 1];
    #pragma unroll 8
    for (int d = 0; d < 64; d++) {
        float h = hns[w][d];
        float2 wv = *(const float2*)(nW2t + d*64 + lane*2);
        o0 = fmaf(h, wv.x, o0);
        o1 = fmaf(h, wv.y, o1);
    }
    size_t ob = (size_t)dst*64 + lane*2;
    out[ob]     = fmaxf(o0, 0.f);
    out[ob + 1] = fmaxf(o1, 0.f);
}

// ---------------- launcher ----------------
extern "C" void kernel_launch(void* const* d_in, const int* in_sizes, int n_in,
                              void* d_out, int out_size)
{
    // Two plausible input orders: setup_inputs dict order vs reference signature order.
    // Disambiguate via in_sizes[3] (e_len has 262144 elems; t2v_w has 7).
    int iNF, iEF, iET, iLEN, iSRC, iT2W, iT2B, iT2W0, iT2B0;
    int iEWih, iEWhh, iEBih, iEBhh, iAWih, iAWhh, iABih, iABhh;
    int iATT, iEOW, iEOB, iNW, iNB;
    if (in_sizes[3] == E_TOT) {
        // dict order
        iNF = 0; iEF = 1; iET = 2; iLEN = 3; iSRC = 4;
        iT2W = 5; iT2B = 6; iT2W0 = 7; iT2B0 = 8;
        iEWih = 9; iEWhh = 10; iEBih = 11; iEBhh = 12;
        iAWih = 13; iAWhh = 14; iABih = 15; iABhh = 16;
        iATT = 17; iEOW = 18; iEOB = 19; iNW = 20; iNB = 21;
    } else {
        // signature order
        iNF = 0; iEF = 1; iET = 2;
        iT2W = 3; iT2B = 4; iT2W0 = 5; iT2B0 = 6;
        iEWih = 7; iEWhh = 8; iEBih = 9; iEBhh = 10;
        iAWih = 11; iAWhh = 12; iABih = 13; iABhh = 14;
        iATT = 15; iEOW = 16; iEOB = 17; iNW = 18; iNB = 19;
        iLEN = 20; iSRC = 21;
    }

    const float* nf   = (const float*)d_in[iNF];
    const float* ef   = (const float*)d_in[iEF];
    const float* et   = (const float*)d_in[iET];
    const int*   elen = (const int*)  d_in[iLEN];
    const int*   esrc = (const int*)  d_in[iSRC];
    const float* t2w  = (const float*)d_in[iT2W];
    const float* t2b  = (const float*)d_in[iT2B];
    const float* t2w0 = (const float*)d_in[iT2W0];
    const float* t2b0 = (const float*)d_in[iT2B0];
    const float* eWih = (const float*)d_in[iEWih];
    const float* eWhh = (const float*)d_in[iEWhh];
    const float* eBih = (const float*)d_in[iEBih];
    const float* eBhh = (const float*)d_in[iEBhh];
    const float* aWih = (const float*)d_in[iAWih];
    const float* aWhh = (const float*)d_in[iAWhh];
    const float* aBih = (const float*)d_in[iABih];
    const float* aBhh = (const float*)d_in[iABhh];
    const float* attn = (const float*)d_in[iATT];
    const float* eOW  = (const float*)d_in[iEOW];
    const float* eOB  = (const float*)d_in[iEOB];
    const float* nW   = (const float*)d_in[iNW];
    const float* nB   = (const float*)d_in[iNB];
    float* out = (float*)d_out;

    // bucketing
    zero_cnt_kernel<<<1, 32>>>();
    hist_kernel<<<256, 256>>>(elen);
    scan_kernel<<<1, 1>>>();
    scatter_kernel<<<E_TOT/256, 256>>>(elen);

    // projections (independent of LSTM)
    proj_kernel<<<dim3(N_SRC/16, 2), 256>>>(nf, eOW, nW);

    // LSTM (both LSTMs via blockIdx.y)
    const int lstm_smem = (PD*G4 + G4 + EB*PD + 16) * 4 + (EB + EB + 1) * 4;
    static int smem_set = 0;
    if (!smem_set) {
        cudaFuncSetAttribute(lstm_kernel, cudaFuncAttributeMaxDynamicSharedMemorySize, lstm_smem);
        smem_set = 1;
    }
    lstm_kernel<<<dim3(E_TOT/EB, 2), 256, lstm_smem>>>(
        ef, et, elen, t2w, t2b, t2w0, t2b0,
        eWih, eWhh, eBih, eBhh, aWih, aWhh, aBih, aBhh);

    // edge epilogue
    edgem_kernel<<<E_TOT/64, 256>>>(eOW, eOB, attn, esrc);

    // per-dst sparsemax + final
    dst_kernel<<<N_DST/8, 256>>>(nW, nB, out);
}

// round 2
// speedup vs baseline: 1.0020x; 1.0020x over previous
#include <cuda_runtime.h>
#include <math.h>
#include <stdint.h>

#define N_SRC 16384
#define N_DST 8192
#define KNB 32
#define E_TOT (N_DST*KNB)   // 262144
#define T 16
#define H 64
#define D_INP 16
#define PD 80               // D_INP + H
#define G4 256              // 4*H
#define EB 64               // edges per LSTM block

// ---------------- scratch (static device memory; no allocs) ----------------
__device__ float g_eout[(size_t)E_TOT*H];
__device__ float g_aout[(size_t)E_TOT*H];
__device__ float g_m[(size_t)E_TOT*H];
__device__ float g_a[E_TOT];
__device__ float g_P[N_SRC*H];
__device__ float g_Q[N_DST*H];
__device__ int   g_list[E_TOT];
__device__ int   g_cnt[T];
__device__ int   g_cur[T];

// ---------------- bucketing ----------------
__global__ void zero_cnt_kernel() {
    if (threadIdx.x < T) g_cnt[threadIdx.x] = 0;
}

__global__ void hist_kernel(const int* __restrict__ elen) {
    __shared__ int h[T];
    if (threadIdx.x < T) h[threadIdx.x] = 0;
    __syncthreads();
    int i = blockIdx.x * blockDim.x + threadIdx.x;
    int stride = gridDim.x * blockDim.x;
    for (; i < E_TOT; i += stride) atomicAdd(&h[elen[i] - 1], 1);
    __syncthreads();
    if (threadIdx.x < T) atomicAdd(&g_cnt[threadIdx.x], h[threadIdx.x]);
}

__global__ void scan_kernel() {
    // single thread; longest buckets first (better tail behavior)
    int off = 0;
    for (int l = T - 1; l >= 0; --l) { g_cur[l] = off; off += g_cnt[l]; }
}

__global__ void scatter_kernel(const int* __restrict__ elen) {
    int i = blockIdx.x * blockDim.x + threadIdx.x;
    if (i >= E_TOT) return;
    int l = elen[i] - 1;
    unsigned act = __activemask();
    unsigned mask = __match_any_sync(act, l);
    int lane = threadIdx.x & 31;
    int leader = __ffs(mask) - 1;
    int rank = __popc(mask & ((1u << lane) - 1));
    int base = 0;
    if (lane == leader) base = atomicAdd(&g_cur[l], __popc(mask));
    base = __shfl_sync(mask, base, leader);
    g_list[base + rank] = i;
}

// ---------------- LSTM (the hot kernel) ----------------
// block: 256 threads, 64 edges, one LSTM (blockIdx.y selects e/a).
// smem: Ws[80][256] combined [Wih;Whh] (row p, col j), bias[256],
//       As[64][80] = [x_t | h], t2v params, edge idx/len.
__global__ void __launch_bounds__(256, 2) lstm_kernel(
    const float* __restrict__ ef, const float* __restrict__ et,
    const int*   __restrict__ elen,
    const float* __restrict__ t2v_w,  const float* __restrict__ t2v_b,
    const float* __restrict__ t2v_w0, const float* __restrict__ t2v_b0,
    const float* __restrict__ Wih_e, const float* __restrict__ Whh_e,
    const float* __restrict__ bih_e, const float* __restrict__ bhh_e,
    const float* __restrict__ Wih_a, const float* __restrict__ Whh_a,
    const float* __restrict__ bih_a, const float* __restrict__ bhh_a)
{
    extern __shared__ float sm[];
    float* Ws  = sm;                  // 80*256 = 20480
    float* bs  = Ws + PD*G4;          // 256
    float* As  = bs + G4;             // 64*80 = 5120
    float* tv  = As + EB*PD;          // 16
    int*   sidx = (int*)(tv + 16);    // 64
    int*   slen = sidx + EB;          // 64
    int*   smax = slen + EB;          // 1

    const int tid = threadIdx.x;
    const bool isA = (blockIdx.y != 0);
    const float* Wih = isA ? Wih_a : Wih_e;
    const float* Whh = isA ? Whh_a : Whh_e;
    const float* bih = isA ? bih_a : bih_e;
    const float* bhh = isA ? bhh_a : bhh_e;
    float* gout = isA ? g_aout : g_eout;

    for (int idx = tid; idx < PD*G4; idx += 256) {
        int p = idx >> 8, j = idx & 255;
        Ws[idx] = (p < D_INP) ? Wih[j*D_INP + p] : Whh[j*H + (p - D_INP)];
    }
    if (tid < G4) bs[tid] = bih[tid] + bhh[tid];
    if (tid < 7) { tv[tid] = t2v_w[tid]; tv[7 + tid] = t2v_b[tid]; }
    if (tid == 0) { tv[14] = t2v_w0[0]; tv[15] = t2v_b0[0]; *smax = 0; }
    if (tid < EB) {
        int eg = g_list[blockIdx.x * EB + tid];
        sidx[tid] = eg;
        int l = elen[eg];
        slen[tid] = l;
        atomicMax(smax, l);
    }
    for (int idx = tid; idx < EB*PD; idx += 256) As[idx] = 0.f;
    __syncthreads();

    const int tm = tid >> 5;        // 0..7  (edge group)
    const int tn = tid & 31;        // 0..31 (h-dim pair)
    int lens[8];
    #pragma unroll
    for (int i = 0; i < 8; i++) lens[i] = slen[tm*8 + i];
    const int maxlen = *smax;

    float c[16], hl[16];
    #pragma unroll
    for (int i = 0; i < 16; i++) { c[i] = 0.f; hl[i] = 0.f; }

    for (int t = 0; t < maxlen; ++t) {
        __syncthreads();   // prev-step GEMM reads of x done; prev h writes visible
        // fill x_t = [edge_feats(8) | sin(tau*w+b)(7) | tau*w0+b0]
        #pragma unroll
        for (int s = 0; s < 4; s++) {
            int idx = tid + 256*s;
            int el = idx >> 4, col = idx & 15;
            int eg = sidx[el];
            float v;
            if (col < 8) {
                v = ef[((size_t)eg*T + t)*8 + col];
            } else {
                float tau = et[(size_t)eg*T + t];
                v = (col < 15) ? __sinf(fmaf(tau, tv[col-8], tv[7 + col-8]))
                               : fmaf(tau, tv[14], tv[15]);
            }
            As[el*PD + col] = v;
        }
        __syncthreads();

        // gates[64 edges][256] = As @ Ws + bias ; per-thread 8x8 tile
        // col(j) = (j>>1)*64 + tn*2 + (j&1)  -> j pairs = {i,f,g,o} x 2 hdims
        float acc[8][8];
        #pragma unroll
        for (int i = 0; i < 8; i++) {
            #pragma unroll
            for (int j = 0; j < 8; j++) acc[i][j] = bs[(j>>1)*64 + tn*2 + (j&1)];
        }
        #pragma unroll 2
        for (int p = 0; p < PD; p++) {
            const float* wrow = Ws + p*G4 + tn*2;
            float2 b0 = *(const float2*)(wrow);
            float2 b1 = *(const float2*)(wrow + 64);
            float2 b2 = *(const float2*)(wrow + 128);
            float2 b3 = *(const float2*)(wrow + 192);
            #pragma unroll
            for (int i = 0; i < 8; i++) {
                float a = As[(tm*8 + i)*PD + p];
                acc[i][0] = fmaf(a, b0.x, acc[i][0]);
                acc[i][1] = fmaf(a, b0.y, acc[i][1]);
                acc[i][2] = fmaf(a, b1.x, acc[i][2]);
                acc[i][3] = fmaf(a, b1.y, acc[i][3]);
                acc[i][4] = fmaf(a, b2.x, acc[i][4]);
                acc[i][5] = fmaf(a, b2.y, acc[i][5]);
                acc[i][6] = fmaf(a, b3.x, acc[i][6]);
                acc[i][7] = fmaf(a, b3.y, acc[i][7]);
            }
        }
        __syncthreads();   // all GEMM reads done; safe to overwrite h in As

        // LSTM cell (register-local), write new h into As, latch hlast
        #pragma unroll
        for (int i = 0; i < 8; i++) {
            #pragma unroll
            for (int hs = 0; hs < 2; hs++) {
                int ridx = i*2 + hs;
                float iv = 1.f / (1.f + __expf(-acc[i][0 + hs]));
                float fv = 1.f / (1.f + __expf(-acc[i][2 + hs]));
                float gv = tanhf(acc[i][4 + hs]);
                float ov = 1.f / (1.f + __expf(-acc[i][6 + hs]));
                float cn = fmaf(fv, c[ridx], iv * gv);
                c[ridx] = cn;
                float hh = ov * tanhf(cn);
                As[(tm*8 + i)*PD + D_INP + tn*2 + hs] = hh;
                if (t < lens[i]) hl[ridx] = hh;
            }
        }
    }

    #pragma unroll
    for (int i = 0; i < 8; i++) {
        size_t base = (size_t)sidx[tm*8 + i] * H + tn*2;
        gout[base]     = hl[i*2];
        gout[base + 1] = hl[i*2 + 1];
    }
}

// ---------------- projection precompute: P = nf@W1^T, Q = nf[:8192]@nW1^T ----------------
__global__ void proj_kernel(const float* __restrict__ nf,
                            const float* __restrict__ eW,
                            const float* __restrict__ nW)
{
    __shared__ float Wt[64*64];   // Wt[d*64+j] = W[j*128+d]
    __shared__ float xs[16*64];
    const float* W = blockIdx.y ? nW : eW;
    float* out = blockIdx.y ? g_Q : g_P;
    int nrows = blockIdx.y ? N_DST : N_SRC;
    int r0 = blockIdx.x * 16;
    if (r0 >= nrows) return;
    int tid = threadIdx.x;
    for (int idx = tid; idx < 4096; idx += 256) {
        int d = idx >> 6, j = idx & 63;
        Wt[idx] = W[j*128 + d];
    }
    for (int idx = tid; idx < 16*64; idx += 256) xs[idx] = nf[(size_t)r0*64 + idx];
    __syncthreads();
    for (int o = tid; o < 1024; o += 256) {
        int ri = o >> 6, j = o & 63;
        float s = 0.f;
        #pragma unroll
        for (int d = 0; d < 64; d++) s = fmaf(xs[ri*64 + d], Wt[d*64 + j], s);
        out[(size_t)(r0 + ri)*64 + j] = s;
    }
}

// ---------------- edge epilogue: m = relu(P[src] + e_out@W2^T + b), a = lrelu(a_out@attn) ----------------
__global__ void __launch_bounds__(256) edgem_kernel(
    const float* __restrict__ eW, const float* __restrict__ eb,
    const float* __restrict__ attn, const int* __restrict__ esrc)
{
    __shared__ float W2t[64*64];   // [d][j] = eW[j*128+64+d]
    __shared__ float eo[64*64];    // e_out tile [e][d]
    __shared__ float att[64];
    __shared__ float bsh[64];
    int tid = threadIdx.x;
    size_t e0 = (size_t)blockIdx.x * 64;
    for (int idx = tid; idx < 4096; idx += 256) {
        int d = idx >> 6, j = idx & 63;
        W2t[idx] = eW[j*128 + 64 + d];
    }
    if (tid < 64) { att[tid] = attn[tid]; bsh[tid] = eb[tid]; }
    for (int idx = tid; idx < 4096; idx += 256) eo[idx] = g_eout[e0*64 + idx];
    __syncthreads();

    int tm = tid >> 5, tn = tid & 31;
    float acc[8][2];
    #pragma unroll
    for (int i = 0; i < 8; i++) { acc[i][0] = bsh[tn*2]; acc[i][1] = bsh[tn*2 + 1]; }
    #pragma unroll 4
    for (int d = 0; d < 64; d++) {
        float2 w = *(const float2*)(W2t + d*64 + tn*2);
        #pragma unroll
        for (int i = 0; i < 8; i++) {
            float a = eo[(tm*8 + i)*64 + d];
            acc[i][0] = fmaf(a, w.x, acc[i][0]);
            acc[i][1] = fmaf(a, w.y, acc[i][1]);
        }
    }
    #pragma unroll
    for (int i = 0; i < 8; i++) {
        size_t e = e0 + tm*8 + i;
        int src = esrc[e];
        float2 pv = *(const float2*)(g_P + (size_t)src*64 + tn*2);
        float m0 = fmaxf(acc[i][0] + pv.x, 0.f);
        float m1 = fmaxf(acc[i][1] + pv.y, 0.f);
        *(float2*)(g_m + e*64 + tn*2) = make_float2(m0, m1);
    }
    if (tid < 64) {
        size_t e = e0 + tid;
        const float4* ar = (const float4*)(g_aout + e*64);
        float s = 0.f;
        #pragma unroll
        for (int d = 0; d < 16; d++) {
            float4 v = ar[d];
            s += v.x*att[d*4] + v.y*att[d*4+1] + v.z*att[d*4+2] + v.w*att[d*4+3];
        }
        g_a[e] = (s > 0.f) ? s : 0.01f*s;
    }
}

// ---------------- per-dst: sparsemax + aggregate + final MLP ----------------
__global__ void __launch_bounds__(256) dst_kernel(
    const float* __restrict__ nW, const float* __restrict__ nb,
    float* __restrict__ out)
{
    __shared__ float nW2t[64*64];   // [d][j] = nW[j*128+64+d]
    __shared__ float nbs[64];
    __shared__ float hns[8][64];
    int tid = threadIdx.x;
    for (int idx = tid; idx < 4096; idx += 256) {
        int d = idx >> 6, j = idx & 63;
        nW2t[idx] = nW[j*128 + 64 + d];
    }
    if (tid < 64) nbs[tid] = nb[tid];
    __syncthreads();

    int w = tid >> 5, lane = tid & 31;
    int dst = blockIdx.x * 8 + w;
    const unsigned FULL = 0xffffffffu;

    float av = g_a[(size_t)dst*KNB + lane];
    float mx = av;
    #pragma unroll
    for (int o = 16; o > 0; o >>= 1) mx = fmaxf(mx, __shfl_xor_sync(FULL, mx, o));
    float z = av - mx;

    // bitonic sort, descending across lanes
    float v = z;
    #pragma unroll
    for (int k = 2; k <= 32; k <<= 1) {
        #pragma unroll
        for (int j = k >> 1; j > 0; j >>= 1) {
            float o = __shfl_xor_sync(FULL, v, j);
            bool lower = (lane & j) == 0;
            bool asc = (lane & k) != 0;
            v = (lower == asc) ? fminf(v, o) : fmaxf(v, o);
        }
    }
    // inclusive cumsum of sorted values
    float cs = v;
    #pragma unroll
    for (int o = 1; o < 32; o <<= 1) {
        float t = __shfl_up_sync(FULL, cs, o);
        if (lane >= o) cs += t;
    }
    float r = (float)(lane + 1);
    bool gt = (1.f + r*v) > cs;
    float kk = gt ? r : 0.f;
    float sz = gt ? v : 0.f;
    #pragma unroll
    for (int o = 16; o > 0; o >>= 1) {
        kk = fmaxf(kk, __shfl_xor_sync(FULL, kk, o));
        sz += __shfl_xor_sync(FULL, sz, o);
    }
    float tau = (sz - 1.f) / kk;
    float alpha = fmaxf(z - tau, 0.f);

    // h_neigh = sum_k alpha_k * m[dst*K+k]; lane holds dims 2*lane, 2*lane+1
    float hn0 = 0.f, hn1 = 0.f;
    #pragma unroll
    for (int k2 = 0; k2 < 32; k2++) {
        float al = __shfl_sync(FULL, alpha, k2);
        if (al > 0.f) {
            const float2 mv = *(const float2*)(g_m + ((size_t)dst*KNB + k2)*64 + lane*2);
            hn0 = fmaf(al, mv.x, hn0);
            hn1 = fmaf(al, mv.y, hn1);
        }
    }
    hns[w][lane*2]     = hn0;
    hns[w][lane*2 + 1] = hn1;
    __syncwarp();

    float o0 = nbs[lane*2]     + g_Q[(size_t)dst*64 + lane*2];
    float o1 = nbs[lane*2 + 1] + g_Q[(size_t)dst*64 + lane*2 + 1];
    #pragma unroll 8
    for (int d = 0; d < 64; d++) {
        float h = hns[w][d];
        float2 wv = *(const float2*)(nW2t + d*64 + lane*2);
        o0 = fmaf(h, wv.x, o0);
        o1 = fmaf(h, wv.y, o1);
    }
    size_t ob = (size_t)dst*64 + lane*2;
    out[ob]     = fmaxf(o0, 0.f);
    out[ob + 1] = fmaxf(o1, 0.f);
}

// ---------------- launcher ----------------
extern "C" void kernel_launch(void* const* d_in, const int* in_sizes, int n_in,
                              void* d_out, int out_size)
{
    // Two plausible input orders: setup_inputs dict order vs reference signature order.
    // Disambiguate via in_sizes[3] (e_len has 262144 elems; t2v_w has 7).
    int iNF, iEF, iET, iLEN, iSRC, iT2W, iT2B, iT2W0, iT2B0;
    int iEWih, iEWhh, iEBih, iEBhh, iAWih, iAWhh, iABih, iABhh;
    int iATT, iEOW, iEOB, iNW, iNB;
    if (in_sizes[3] == E_TOT) {
        // dict order
        iNF = 0; iEF = 1; iET = 2; iLEN = 3; iSRC = 4;
        iT2W = 5; iT2B = 6; iT2W0 = 7; iT2B0 = 8;
        iEWih = 9; iEWhh = 10; iEBih = 11; iEBhh = 12;
        iAWih = 13; iAWhh = 14; iABih = 15; iABhh = 16;
        iATT = 17; iEOW = 18; iEOB = 19; iNW = 20; iNB = 21;
    } else {
        // signature order
        iNF = 0; iEF = 1; iET = 2;
        iT2W = 3; iT2B = 4; iT2W0 = 5; iT2B0 = 6;
        iEWih = 7; iEWhh = 8; iEBih = 9; iEBhh = 10;
        iAWih = 11; iAWhh = 12; iABih = 13; iABhh = 14;
        iATT = 15; iEOW = 16; iEOB = 17; iNW = 18; iNB = 19;
        iLEN = 20; iSRC = 21;
    }

    const float* nf   = (const float*)d_in[iNF];
    const float* ef   = (const float*)d_in[iEF];
    const float* et   = (const float*)d_in[iET];
    const int*   elen = (const int*)  d_in[iLEN];
    const int*   esrc = (const int*)  d_in[iSRC];
    const float* t2w  = (const float*)d_in[iT2W];
    const float* t2b  = (const float*)d_in[iT2B];
    const float* t2w0 = (const float*)d_in[iT2W0];
    const float* t2b0 = (const float*)d_in[iT2B0];
    const float* eWih = (const float*)d_in[iEWih];
    const float* eWhh = (const float*)d_in[iEWhh];
    const float* eBih = (const float*)d_in[iEBih];
    const float* eBhh = (const float*)d_in[iEBhh];
    const float* aWih = (const float*)d_in[iAWih];
    const float* aWhh = (const float*)d_in[iAWhh];
    const float* aBih = (const float*)d_in[iABih];
    const float* aBhh = (const float*)d_in[iABhh];
    const float* attn = (const float*)d_in[iATT];
    const float* eOW  = (const float*)d_in[iEOW];
    const float* eOB  = (const float*)d_in[iEOB];
    const float* nW   = (const float*)d_in[iNW];
    const float* nB   = (const float*)d_in[iNB];
    float* out = (float*)d_out;

    // bucketing
    zero_cnt_kernel<<<1, 32>>>();
    hist_kernel<<<256, 256>>>(elen);
    scan_kernel<<<1, 1>>>();
    scatter_kernel<<<E_TOT/256, 256>>>(elen);

    // projections (independent of LSTM)
    proj_kernel<<<dim3(N_SRC/16, 2), 256>>>(nf, eOW, nW);

    // LSTM (both LSTMs via blockIdx.y)
    const int lstm_smem = (PD*G4 + G4 + EB*PD + 16) * 4 + (EB + EB + 1) * 4;
    static int smem_set = 0;
    if (!smem_set) {
        cudaFuncSetAttribute(lstm_kernel, cudaFuncAttributeMaxDynamicSharedMemorySize, lstm_smem);
        smem_set = 1;
    }
    lstm_kernel<<<dim3(E_TOT/EB, 2), 256, lstm_smem>>>(
        ef, et, elen, t2w, t2b, t2w0, t2b0,
        eWih, eWhh, eBih, eBhh, aWih, aWhh, aBih, aBhh);

    // edge epilogue
    edgem_kernel<<<E_TOT/64, 256>>>(eOW, eOB, attn, esrc);

    // per-dst sparsemax + final
    dst_kernel<<<N_DST/8, 256>>>(nW, nB, out);
}

// round 4
// speedup vs baseline: 1.5289x; 1.5259x over previous
#include <cuda_runtime.h>
#include <cuda_bf16.h>
#include <math.h>
#include <stdint.h>

#define N_SRC 16384
#define N_DST 8192
#define KNB 32
#define E_TOT (N_DST*KNB)
#define T 16
#define H 64
#define TILE 128

// ---- scratch ----
__device__ float g_eout[(size_t)E_TOT*H];
__device__ float g_aout[(size_t)E_TOT*H];
__device__ float g_m[(size_t)E_TOT*H];
__device__ float g_a[E_TOT];
__device__ float g_P[N_SRC*H];
__device__ float g_Q[N_DST*H];
__device__ int   g_list[E_TOT];
__device__ int   g_cnt[T];
__device__ int   g_cur[T];

// ---- smem byte map (dynamic) ----
#define OFF_B0   0            // Whh_hi  [256n][64k] bf16, 32768
#define OFF_B1   32768        // Whh_lo
#define OFF_B2   65536        // x-combo weights
#define OFF_AHI  98304        // h_hi [128e][64k], 16384
#define OFF_ALO  114688       // h_lo
#define OFF_AX   131072       // x combo [128e][64k]
#define OFF_SIDX 147456
#define OFF_SLEN 147968
#define OFF_TV   148480
#define OFF_SMAX 148544
#define LSTM_SMEM 148608

__device__ __forceinline__ uint32_t smem_u32(const void* p){
    uint32_t a; asm("{ .reg .u64 t; cvta.to.shared.u64 t, %1; cvt.u32.u64 %0, t; }":"=r"(a):"l"(p)); return a;
}
// swizzled addresses: row stride 128B, 16B-chunk XOR by (row&7)
__device__ __forceinline__ uint32_t sw_mat(uint32_t base, int row, int kch){
    return base + (uint32_t)row*128u + ((uint32_t)((kch ^ (row & 7)) & 7) << 4);
}
__device__ __forceinline__ uint32_t sw_el(uint32_t base, int row, int k){
    return base + (uint32_t)row*128u + ((uint32_t)(((k>>3) ^ (row & 7)) & 7) << 4) + ((uint32_t)(k & 7) << 1);
}
__device__ __forceinline__ void ldm4(uint32_t addr, uint32_t &r0, uint32_t &r1, uint32_t &r2, uint32_t &r3){
    asm volatile("ldmatrix.sync.aligned.m8n8.x4.shared.b16 {%0,%1,%2,%3}, [%4];"
        : "=r"(r0),"=r"(r1),"=r"(r2),"=r"(r3) : "r"(addr));
}
__device__ __forceinline__ void mma_bf(float* c, uint32_t a0,uint32_t a1,uint32_t a2,uint32_t a3,
                                       uint32_t b0, uint32_t b1){
    asm volatile("mma.sync.aligned.m16n8k16.row.col.f32.bf16.bf16.f32 "
        "{%0,%1,%2,%3}, {%4,%5,%6,%7}, {%8,%9}, {%0,%1,%2,%3};"
        : "+f"(c[0]),"+f"(c[1]),"+f"(c[2]),"+f"(c[3])
        : "r"(a0),"r"(a1),"r"(a2),"r"(a3),"r"(b0),"r"(b1));
}
__device__ __forceinline__ float sigf(float x){ return __fdividef(1.f, 1.f + __expf(-x)); }
__device__ __forceinline__ float thf(float x) { return 1.f - 2.f*__fdividef(1.f, 1.f + __expf(2.f*x)); }
__device__ __forceinline__ uint32_t pack_bf2(float a, float b, float &ra, float &rb){
    __nv_bfloat162 v; v.x = __float2bfloat16(a); v.y = __float2bfloat16(b);
    ra = __bfloat162float(v.x); rb = __bfloat162float(v.y);
    return *(uint32_t*)&v;
}

// ---- bucketing ----
__global__ void zero_cnt_kernel(){ if (threadIdx.x < T) g_cnt[threadIdx.x] = 0; }
__global__ void hist_kernel(const int* __restrict__ elen){
    __shared__ int h[T];
    if (threadIdx.x < T) h[threadIdx.x] = 0;
    __syncthreads();
    int i = blockIdx.x*blockDim.x + threadIdx.x, s = gridDim.x*blockDim.x;
    for (; i < E_TOT; i += s) atomicAdd(&h[elen[i]-1], 1);
    __syncthreads();
    if (threadIdx.x < T) atomicAdd(&g_cnt[threadIdx.x], h[threadIdx.x]);
}
__global__ void scan_kernel(){
    int off = 0;
    for (int l = T-1; l >= 0; --l){ g_cur[l] = off; off += g_cnt[l]; }
}
__global__ void scatter_kernel(const int* __restrict__ elen){
    int i = blockIdx.x*blockDim.x + threadIdx.x;
    if (i >= E_TOT) return;
    int l = elen[i]-1;
    unsigned act = __activemask();
    unsigned mask = __match_any_sync(act, l);
    int lane = threadIdx.x & 31, leader = __ffs(mask)-1;
    int rank = __popc(mask & ((1u<<lane)-1));
    int base = 0;
    if (lane == leader) base = atomicAdd(&g_cur[l], __popc(mask));
    base = __shfl_sync(mask, base, leader);
    g_list[base+rank] = i;
}

// ---- LSTM via mma.sync bf16 split ----
__global__ void __launch_bounds__(512, 1) lstm_hmma_kernel(
    const float* __restrict__ ef, const float* __restrict__ et,
    const int*   __restrict__ elen,
    const float* __restrict__ t2v_w,  const float* __restrict__ t2v_b,
    const float* __restrict__ t2v_w0, const float* __restrict__ t2v_b0,
    const float* __restrict__ Wih_e, const float* __restrict__ Whh_e,
    const float* __restrict__ bih_e, const float* __restrict__ bhh_e,
    const float* __restrict__ Wih_a, const float* __restrict__ Whh_a,
    const float* __restrict__ bih_a, const float* __restrict__ bhh_a)
{
    extern __shared__ char smem[];
    const uint32_t sb = smem_u32(smem);
    int*   sidx = (int*)(smem + OFF_SIDX);
    int*   slen = (int*)(smem + OFF_SLEN);
    float* sTv  = (float*)(smem + OFF_TV);
    int*   smax = (int*)(smem + OFF_SMAX);

    const int tid = threadIdx.x, wid = tid >> 5, lane = tid & 31;
    const bool isA = (blockIdx.y != 0);
    const float* Wih = isA ? Wih_a : Wih_e;
    const float* Whh = isA ? Whh_a : Whh_e;
    const float* bih = isA ? bih_a : bih_e;
    const float* bhh = isA ? bhh_a : bhh_e;
    float* gout = isA ? g_aout : g_eout;

    if (tid == 0) *smax = 0;
    if (tid < 16){
        float v;
        if (tid < 7) v = t2v_w[tid]; else if (tid < 14) v = t2v_b[tid-7];
        else if (tid == 14) v = t2v_w0[0]; else v = t2v_b0[0];
        sTv[tid] = v;
    }
    if (tid < TILE){
        int eg = g_list[blockIdx.x*TILE + tid];
        sidx[tid] = eg;
        int l = elen[eg];
        slen[tid] = l;
        atomicMax(smax, l);
    }
    // zero A regions (48KB)
    {
        float4 z = make_float4(0.f,0.f,0.f,0.f);
        float4* pa = (float4*)(smem + OFF_AHI);
        for (int i = tid; i < 49152/16; i += 512) pa[i] = z;
    }
    // B fill: j = row (unit-major gate layout), srcj = pytorch row
    {
        int j = tid >> 1, half = tid & 1;
        int srcj = (j & 3)*64 + (j >> 2);
        const float* whr = Whh + srcj*64;
        for (int k = half*32; k < half*32 + 32; k++){
            float w = __ldg(whr + k);
            __nv_bfloat16 hb = __float2bfloat16(w);
            __nv_bfloat16 lb = __float2bfloat16(w - __bfloat162float(hb));
            *(__nv_bfloat16*)(smem + (sw_el(OFF_B0, j, k))) = hb;
            *(__nv_bfloat16*)(smem + (sw_el(OFF_B1, j, k))) = lb;
        }
        const float* wir = Wih + srcj*16;
        if (half == 0){
            for (int kk = 0; kk < 16; kk++){
                float w = __ldg(wir + kk);
                __nv_bfloat16 hb = __float2bfloat16(w);
                __nv_bfloat16 lb = __float2bfloat16(w - __bfloat162float(hb));
                *(__nv_bfloat16*)(smem + sw_el(OFF_B2, j, kk))      = hb;
                *(__nv_bfloat16*)(smem + sw_el(OFF_B2, j, 16 + kk)) = lb;
            }
        } else {
            for (int kk = 0; kk < 16; kk++)
                *(__nv_bfloat16*)(smem + sw_el(OFF_B2, j, 32 + kk)) = __float2bfloat16(__ldg(wir + kk));
            float bv = __ldg(bih + srcj) + __ldg(bhh + srcj);
            __nv_bfloat16 bh = __float2bfloat16(bv);
            __nv_bfloat16 bl = __float2bfloat16(bv - __bfloat162float(bh));
            *(__nv_bfloat16*)(smem + sw_el(OFF_B2, j, 48)) = bh;
            *(__nv_bfloat16*)(smem + sw_el(OFF_B2, j, 49)) = bl;
            for (int kk = 50; kk < 64; kk++)
                *(__nv_bfloat16*)(smem + sw_el(OFF_B2, j, kk)) = __float2bfloat16(0.f);
        }
    }
    __syncthreads();

    const int maxlen = *smax;
    const int pedge = (tid < TILE) ? sidx[tid] : 0;

    // ones cols in Ax (k48,49) + x(0)
    if (tid < TILE){
        __nv_bfloat162 one2; one2.x = __float2bfloat16(1.f); one2.y = one2.x;
        *(uint32_t*)(smem + sw_el(OFF_AX, tid, 48)) = *(uint32_t*)&one2;
        // x(0)
        float x[16];
        const float4* p = (const float4*)(ef + ((size_t)pedge*T + 0)*8);
        float4 v0 = __ldg(p), v1 = __ldg(p+1);
        x[0]=v0.x;x[1]=v0.y;x[2]=v0.z;x[3]=v0.w;x[4]=v1.x;x[5]=v1.y;x[6]=v1.z;x[7]=v1.w;
        float tau = __ldg(et + (size_t)pedge*T + 0);
        #pragma unroll
        for (int k = 0; k < 7; k++) x[8+k] = __sinf(fmaf(tau, sTv[k], sTv[7+k]));
        x[15] = fmaf(tau, sTv[14], sTv[15]);
        #pragma unroll
        for (int u = 0; u < 16; u += 2){
            float ha, hbv;
            uint32_t hi2 = pack_bf2(x[u], x[u+1], ha, hbv);
            __nv_bfloat162 lo; lo.x = __float2bfloat16(x[u]-ha); lo.y = __float2bfloat16(x[u+1]-hbv);
            *(uint32_t*)(smem + sw_el(OFF_AX, tid, u))      = hi2;
            *(uint32_t*)(smem + sw_el(OFF_AX, tid, 16 + u)) = hi2;
            *(uint32_t*)(smem + sw_el(OFF_AX, tid, 32 + u)) = *(uint32_t*)&lo;
        }
    }
    __syncthreads();

    // roles
    const int eg = wid >> 1, nh = wid & 1;
    const int ebase = eg*16, j0 = nh*128;
    const int myedge = ebase + (lane >> 2) + ((lane & 1) ? 8 : 0);
    const int myeg_g = sidx[myedge];
    const int mylen  = slen[myedge];
    const int ubit = (lane >> 1) & 1;

    float acc[64];
    float cst[16];
    #pragma unroll
    for (int i = 0; i < 16; i++) cst[i] = 0.f;

    for (int t = 0; t < maxlen; ++t){
        // prefetch x(t+1)
        float4 pf0, pf1; float ptau = 0.f;
        const bool doPf = (tid < TILE) && (t+1 < maxlen);
        if (doPf){
            const float4* p = (const float4*)(ef + ((size_t)pedge*T + t+1)*8);
            pf0 = __ldg(p); pf1 = __ldg(p+1);
            ptau = __ldg(et + (size_t)pedge*T + t+1);
        }

        #pragma unroll
        for (int i = 0; i < 64; i++) acc[i] = 0.f;

        // seg0+1: A = h_hi, B = Whh_hi then Whh_lo
        #pragma unroll
        for (int ks = 0; ks < 4; ks++){
            uint32_t a0,a1,a2,a3;
            { int r = ebase + (lane & 15); int cc = 2*ks + (lane >> 4);
              ldm4(sw_mat(sb + OFF_AHI, r, cc), a0,a1,a2,a3); }
            int rowb = j0 + ((lane >> 4) << 3) + (lane & 7);
            int chb  = 2*ks + ((lane >> 3) & 1);
            #pragma unroll
            for (int p = 0; p < 8; p++){
                uint32_t b0,b1,b2,b3;
                ldm4(sw_mat(sb + OFF_B0, rowb + p*16, chb), b0,b1,b2,b3);
                mma_bf(&acc[8*p], a0,a1,a2,a3, b0,b1);
                mma_bf(&acc[8*p+4], a0,a1,a2,a3, b2,b3);
            }
            #pragma unroll
            for (int p = 0; p < 8; p++){
                uint32_t b0,b1,b2,b3;
                ldm4(sw_mat(sb + OFF_B1, rowb + p*16, chb), b0,b1,b2,b3);
                mma_bf(&acc[8*p], a0,a1,a2,a3, b0,b1);
                mma_bf(&acc[8*p+4], a0,a1,a2,a3, b2,b3);
            }
        }
        // seg2: A = h_lo, B = Whh_hi
        #pragma unroll
        for (int ks = 0; ks < 4; ks++){
            uint32_t a0,a1,a2,a3;
            { int r = ebase + (lane & 15); int cc = 2*ks + (lane >> 4);
              ldm4(sw_mat(sb + OFF_ALO, r, cc), a0,a1,a2,a3); }
            int rowb = j0 + ((lane >> 4) << 3) + (lane & 7);
            int chb  = 2*ks + ((lane >> 3) & 1);
            #pragma unroll
            for (int p = 0; p < 8; p++){
                uint32_t b0,b1,b2,b3;
                ldm4(sw_mat(sb + OFF_B0, rowb + p*16, chb), b0,b1,b2,b3);
                mma_bf(&acc[8*p], a0,a1,a2,a3, b0,b1);
                mma_bf(&acc[8*p+4], a0,a1,a2,a3, b2,b3);
            }
        }
        // seg3: A = x combo, B = B2
        #pragma unroll
        for (int ks = 0; ks < 4; ks++){
            uint32_t a0,a1,a2,a3;
            { int r = ebase + (lane & 15); int cc = 2*ks + (lane >> 4);
              ldm4(sw_mat(sb + OFF_AX, r, cc), a0,a1,a2,a3); }
            int rowb = j0 + ((lane >> 4) << 3) + (lane & 7);
            int chb  = 2*ks + ((lane >> 3) & 1);
            #pragma unroll
            for (int p = 0; p < 8; p++){
                uint32_t b0,b1,b2,b3;
                ldm4(sw_mat(sb + OFF_B2, rowb + p*16, chb), b0,b1,b2,b3);
                mma_bf(&acc[8*p], a0,a1,a2,a3, b0,b1);
                mma_bf(&acc[8*p+4], a0,a1,a2,a3, b2,b3);
            }
        }

        __syncthreads();   // all GEMM smem reads done

        // write x(t+1)
        if (doPf){
            float x[16];
            x[0]=pf0.x;x[1]=pf0.y;x[2]=pf0.z;x[3]=pf0.w;x[4]=pf1.x;x[5]=pf1.y;x[6]=pf1.z;x[7]=pf1.w;
            #pragma unroll
            for (int k = 0; k < 7; k++) x[8+k] = __sinf(fmaf(ptau, sTv[k], sTv[7+k]));
            x[15] = fmaf(ptau, sTv[14], sTv[15]);
            #pragma unroll
            for (int u = 0; u < 16; u += 2){
                float ha, hbv;
                uint32_t hi2 = pack_bf2(x[u], x[u+1], ha, hbv);
                __nv_bfloat162 lo; lo.x = __float2bfloat16(x[u]-ha); lo.y = __float2bfloat16(x[u+1]-hbv);
                *(uint32_t*)(smem + sw_el(OFF_AX, tid, u))      = hi2;
                *(uint32_t*)(smem + sw_el(OFF_AX, tid, 16 + u)) = hi2;
                *(uint32_t*)(smem + sw_el(OFF_AX, tid, 32 + u)) = *(uint32_t*)&lo;
            }
        }

        // cell update: per tile, reunite gates via shfl.xor(1)
        const bool last = (t == mylen - 1);
        #pragma unroll
        for (int tl = 0; tl < 16; tl++){
            float d0 = acc[4*tl], d1 = acc[4*tl+1], d2 = acc[4*tl+2], d3 = acc[4*tl+3];
            float sx = (lane & 1) ? d0 : d2;
            float sy = (lane & 1) ? d1 : d3;
            float rx = __shfl_xor_sync(0xffffffffu, sx, 1);
            float ry = __shfl_xor_sync(0xffffffffu, sy, 1);
            float gi, gf, gg, go;
            if (lane & 1){ gi = rx; gf = ry; gg = d2; go = d3; }
            else         { gi = d0; gf = d1; gg = rx; go = ry; }
            float iv = sigf(gi), fv = sigf(gf), gv = thf(gg), ov = sigf(go);
            float cn = fmaf(fv, cst[tl], iv*gv);
            cst[tl] = cn;
            float h = ov * thf(cn);
            int u = nh*32 + 2*tl + ubit;
            __nv_bfloat16 hb = __float2bfloat16(h);
            *(__nv_bfloat16*)(smem + sw_el(OFF_AHI, myedge, u)) = hb;
            *(__nv_bfloat16*)(smem + sw_el(OFF_ALO, myedge, u)) = __float2bfloat16(h - __bfloat162float(hb));
            if (last) gout[(size_t)myeg_g*H + u] = h;
        }
        __syncthreads();   // h(t+1), x(t+1) visible
    }
}

// ---- projections: P = nf@eW1^T, Q = nf[:8192]@nW1^T ----
__global__ void proj_kernel(const float* __restrict__ nf,
                            const float* __restrict__ eW, const float* __restrict__ nW)
{
    __shared__ float Wt[64*64];
    __shared__ float xs[16*64];
    const float* W = blockIdx.y ? nW : eW;
    float* out = blockIdx.y ? g_Q : g_P;
    int nrows = blockIdx.y ? N_DST : N_SRC;
    int r0 = blockIdx.x*16;
    if (r0 >= nrows) return;
    int tid = threadIdx.x;
    for (int idx = tid; idx < 4096; idx += 256){ int d = idx>>6, j = idx&63; Wt[idx] = W[j*128 + d]; }
    for (int idx = tid; idx < 1024; idx += 256) xs[idx] = nf[(size_t)r0*64 + idx];
    __syncthreads();
    for (int o = tid; o < 1024; o += 256){
        int ri = o>>6, j = o&63;
        float s = 0.f;
        #pragma unroll
        for (int d = 0; d < 64; d++) s = fmaf(xs[ri*64+d], Wt[d*64+j], s);
        out[(size_t)(r0+ri)*64 + j] = s;
    }
}

// ---- edge epilogue ----
__global__ void __launch_bounds__(256) edgem_kernel(
    const float* __restrict__ eW, const float* __restrict__ eb,
    const float* __restrict__ attn, const int* __restrict__ esrc)
{
    __shared__ float W2t[64*64];
    __shared__ float eo[64*64];
    __shared__ float att[64], bsh[64];
    int tid = threadIdx.x;
    size_t e0 = (size_t)blockIdx.x*64;
    for (int idx = tid; idx < 4096; idx += 256){ int d = idx>>6, j = idx&63; W2t[idx] = eW[j*128 + 64 + d]; }
    if (tid < 64){ att[tid] = attn[tid]; bsh[tid] = eb[tid]; }
    for (int idx = tid; idx < 4096; idx += 256) eo[idx] = g_eout[e0*64 + idx];
    __syncthreads();
    int tm = tid>>5, tn = tid&31;
    float acc[8][2];
    #pragma unroll
    for (int i = 0; i < 8; i++){ acc[i][0] = bsh[tn*2]; acc[i][1] = bsh[tn*2+1]; }
    #pragma unroll 4
    for (int d = 0; d < 64; d++){
        float2 w = *(const float2*)(W2t + d*64 + tn*2);
        #pragma unroll
        for (int i = 0; i < 8; i++){
            float a = eo[(tm*8+i)*64 + d];
            acc[i][0] = fmaf(a, w.x, acc[i][0]);
            acc[i][1] = fmaf(a, w.y, acc[i][1]);
        }
    }
    #pragma unroll
    for (int i = 0; i < 8; i++){
        size_t e = e0 + tm*8 + i;
        int src = esrc[e];
        float2 pv = *(const float2*)(g_P + (size_t)src*64 + tn*2);
        *(float2*)(g_m + e*64 + tn*2) = make_float2(fmaxf(acc[i][0]+pv.x, 0.f), fmaxf(acc[i][1]+pv.y, 0.f));
    }
    if (tid < 64){
        size_t e = e0 + tid;
        const float4* ar = (const float4*)(g_aout + e*64);
        float s = 0.f;
        #pragma unroll
        for (int d = 0; d < 16; d++){
            float4 v = ar[d];
            s += v.x*att[d*4] + v.y*att[d*4+1] + v.z*att[d*4+2] + v.w*att[d*4+3];
        }
        g_a[e] = (s > 0.f) ? s : 0.01f*s;
    }
}

// ---- per-dst: sparsemax + aggregate + final MLP ----
__global__ void __launch_bounds__(256) dst_kernel(
    const float* __restrict__ nW, const float* __restrict__ nb, float* __restrict__ out)
{
    __shared__ float nW2t[64*64];
    __shared__ float nbs[64];
    __shared__ float hns[8][64];
    int tid = threadIdx.x;
    for (int idx = tid; idx < 4096; idx += 256){ int d = idx>>6, j = idx&63; nW2t[idx] = nW[j*128 + 64 + d]; }
    if (tid < 64) nbs[tid] = nb[tid];
    __syncthreads();
    int w = tid>>5, lane = tid&31;
    int dst = blockIdx.x*8 + w;
    const unsigned FULL = 0xffffffffu;

    float av = g_a[(size_t)dst*KNB + lane];
    float mx = av;
    #pragma unroll
    for (int o = 16; o > 0; o >>= 1) mx = fmaxf(mx, __shfl_xor_sync(FULL, mx, o));
    float z = av - mx;
    float v = z;
    #pragma unroll
    for (int k = 2; k <= 32; k <<= 1){
        #pragma unroll
        for (int j = k>>1; j > 0; j >>= 1){
            float o = __shfl_xor_sync(FULL, v, j);
            bool lower = (lane & j) == 0, asc = (lane & k) != 0;
            v = (lower == asc) ? fminf(v, o) : fmaxf(v, o);
        }
    }
    float cs = v;
    #pragma unroll
    for (int o = 1; o < 32; o <<= 1){
        float t = __shfl_up_sync(FULL, cs, o);
        if (lane >= o) cs += t;
    }
    float r = (float)(lane+1);
    bool gt = (1.f + r*v) > cs;
    float kk = gt ? r : 0.f, sz = gt ? v : 0.f;
    #pragma unroll
    for (int o = 16; o > 0; o >>= 1){
        kk = fmaxf(kk, __shfl_xor_sync(FULL, kk, o));
        sz += __shfl_xor_sync(FULL, sz, o);
    }
    float alpha = fmaxf(z - (sz - 1.f)/kk, 0.f);

    float hn0 = 0.f, hn1 = 0.f;
    #pragma unroll
    for (int k2 = 0; k2 < 32; k2++){
        float al = __shfl_sync(FULL, alpha, k2);
        if (al > 0.f){
            const float2 mv = *(const float2*)(g_m + ((size_t)dst*KNB + k2)*64 + lane*2);
            hn0 = fmaf(al, mv.x, hn0);
            hn1 = fmaf(al, mv.y, hn1);
        }
    }
    hns[w][lane*2] = hn0; hns[w][lane*2+1] = hn1;
    __syncwarp();
    float o0 = nbs[lane*2]   + g_Q[(size_t)dst*64 + lane*2];
    float o1 = nbs[lane*2+1] + g_Q[(size_t)dst*64 + lane*2+1];
    #pragma unroll 8
    for (int d = 0; d < 64; d++){
        float h = hns[w][d];
        float2 wv = *(const float2*)(nW2t + d*64 + lane*2);
        o0 = fmaf(h, wv.x, o0);
        o1 = fmaf(h, wv.y, o1);
    }
    size_t ob = (size_t)dst*64 + lane*2;
    out[ob] = fmaxf(o0, 0.f);
    out[ob+1] = fmaxf(o1, 0.f);
}

// ---- launcher ----
extern "C" void kernel_launch(void* const* d_in, const int* in_sizes, int n_in,
                              void* d_out, int out_size)
{
    int iNF,iEF,iET,iLEN,iSRC,iT2W,iT2B,iT2W0,iT2B0;
    int iEWih,iEWhh,iEBih,iEBhh,iAWih,iAWhh,iABih,iABhh,iATT,iEOW,iEOB,iNW,iNB;
    if (in_sizes[3] == E_TOT){
        iNF=0;iEF=1;iET=2;iLEN=3;iSRC=4;iT2W=5;iT2B=6;iT2W0=7;iT2B0=8;
        iEWih=9;iEWhh=10;iEBih=11;iEBhh=12;iAWih=13;iAWhh=14;iABih=15;iABhh=16;
        iATT=17;iEOW=18;iEOB=19;iNW=20;iNB=21;
    } else {
        iNF=0;iEF=1;iET=2;iT2W=3;iT2B=4;iT2W0=5;iT2B0=6;
        iEWih=7;iEWhh=8;iEBih=9;iEBhh=10;iAWih=11;iAWhh=12;iABih=13;iABhh=14;
        iATT=15;iEOW=16;iEOB=17;iNW=18;iNB=19;iLEN=20;iSRC=21;
    }
    const float* nf   = (const float*)d_in[iNF];
    const float* ef   = (const float*)d_in[iEF];
    const float* et   = (const float*)d_in[iET];
    const int*   elen = (const int*)  d_in[iLEN];
    const int*   esrc = (const int*)  d_in[iSRC];
    float* out = (float*)d_out;

    cudaFuncSetAttribute(lstm_hmma_kernel, cudaFuncAttributeMaxDynamicSharedMemorySize, LSTM_SMEM);

    zero_cnt_kernel<<<1, 32>>>();
    hist_kernel<<<256, 256>>>(elen);
    scan_kernel<<<1, 1>>>();
    scatter_kernel<<<E_TOT/256, 256>>>(elen);

    proj_kernel<<<dim3(N_SRC/16, 2), 256>>>(nf, (const float*)d_in[iEOW], (const float*)d_in[iNW]);

    lstm_hmma_kernel<<<dim3(E_TOT/TILE, 2), 512, LSTM_SMEM>>>(
        ef, et, elen,
        (const float*)d_in[iT2W], (const float*)d_in[iT2B],
        (const float*)d_in[iT2W0], (const float*)d_in[iT2B0],
        (const float*)d_in[iEWih], (const float*)d_in[iEWhh],
        (const float*)d_in[iEBih], (const float*)d_in[iEBhh],
        (const float*)d_in[iAWih], (const float*)d_in[iAWhh],
        (const float*)d_in[iABih], (const float*)d_in[iABhh]);

    edgem_kernel<<<E_TOT/64, 256>>>((const float*)d_in[iEOW], (const float*)d_in[iEOB],
                                    (const float*)d_in[iATT], esrc);
    dst_kernel<<<N_DST/8, 256>>>((const float*)d_in[iNW], (const float*)d_in[iNB], out);
}

// round 5
// speedup vs baseline: 2.0982x; 1.3724x over previous
#include <cuda_runtime.h>
#include <cuda_bf16.h>
#include <math.h>
#include <stdint.h>

#define N_SRC 16384
#define N_DST 8192
#define KNB 32
#define E_TOT (N_DST*KNB)
#define T 16
#define H 64
#define TILE 128

// ---- scratch ----
__device__ float g_eout[(size_t)E_TOT*H];
__device__ float g_aout[(size_t)E_TOT*H];
__device__ float g_m[(size_t)E_TOT*H];
__device__ float g_a[E_TOT];
__device__ float g_P[N_SRC*H];
__device__ float g_Q[N_DST*H];
__device__ int   g_list[E_TOT];
__device__ int   g_part[128][16];
__device__ int   g_cur[T];

// ---- smem byte map (dynamic) ----
#define OFF_B0   0            // Whh_hi  [256n][64k] bf16
#define OFF_B1   32768        // Whh_lo
#define OFF_B2   65536        // x-combo weights
#define OFF_AHI  98304        // h_hi [2][128e][64k]
#define OFF_ALO  131072       // h_lo [2]
#define OFF_AX   163840       // x combo [2]
#define OFF_SIDX 196608
#define OFF_SLEN 197120
#define OFF_TV   197632
#define OFF_SMAX 197696
#define LSTM_SMEM 197760

__device__ __forceinline__ uint32_t smem_u32(const void* p){
    uint32_t a; asm("{ .reg .u64 t; cvta.to.shared.u64 t, %1; cvt.u32.u64 %0, t; }":"=r"(a):"l"(p)); return a;
}
__device__ __forceinline__ uint32_t sw_mat(uint32_t base, int row, int kch){
    return base + (uint32_t)row*128u + ((uint32_t)((kch ^ (row & 7)) & 7) << 4);
}
__device__ __forceinline__ uint32_t sw_el(uint32_t base, int row, int k){
    return base + (uint32_t)row*128u + ((uint32_t)(((k>>3) ^ (row & 7)) & 7) << 4) + ((uint32_t)(k & 7) << 1);
}
__device__ __forceinline__ void ldm4(uint32_t addr, uint32_t &r0, uint32_t &r1, uint32_t &r2, uint32_t &r3){
    asm volatile("ldmatrix.sync.aligned.m8n8.x4.shared.b16 {%0,%1,%2,%3}, [%4];"
        : "=r"(r0),"=r"(r1),"=r"(r2),"=r"(r3) : "r"(addr));
}
__device__ __forceinline__ void mma_bf(float* c, uint32_t a0,uint32_t a1,uint32_t a2,uint32_t a3,
                                       uint32_t b0, uint32_t b1){
    asm volatile("mma.sync.aligned.m16n8k16.row.col.f32.bf16.bf16.f32 "
        "{%0,%1,%2,%3}, {%4,%5,%6,%7}, {%8,%9}, {%0,%1,%2,%3};"
        : "+f"(c[0]),"+f"(c[1]),"+f"(c[2]),"+f"(c[3])
        : "r"(a0),"r"(a1),"r"(a2),"r"(a3),"r"(b0),"r"(b1));
}
__device__ __forceinline__ float sigf(float x){ return __fdividef(1.f, 1.f + __expf(-x)); }
__device__ __forceinline__ float thf(float x) { return 1.f - 2.f*__fdividef(1.f, 1.f + __expf(2.f*x)); }
__device__ __forceinline__ uint32_t pack_bf2(float a, float b, float &ra, float &rb){
    __nv_bfloat162 v; v.x = __float2bfloat16(a); v.y = __float2bfloat16(b);
    ra = __bfloat162float(v.x); rb = __bfloat162float(v.y);
    return *(uint32_t*)&v;
}

// ---- bucketing (3 kernels, no zero pass) ----
__global__ void hist_part_kernel(const int* __restrict__ elen){
    __shared__ int h[T];
    if (threadIdx.x < T) h[threadIdx.x] = 0;
    __syncthreads();
    int base = blockIdx.x * 2048;
    for (int i = threadIdx.x; i < 2048; i += 256) atomicAdd(&h[elen[base + i] - 1], 1);
    __syncthreads();
    if (threadIdx.x < T) g_part[blockIdx.x][threadIdx.x] = h[threadIdx.x];
}
__global__ void scan2_kernel(){
    __shared__ int cnt[T];
    if (threadIdx.x < T){
        int s = 0;
        for (int b = 0; b < 128; b++) s += g_part[b][threadIdx.x];
        cnt[threadIdx.x] = s;
    }
    __syncthreads();
    if (threadIdx.x == 0){
        int off = 0;
        for (int l = T-1; l >= 0; --l){ g_cur[l] = off; off += cnt[l]; }
    }
}
__global__ void scatter_kernel(const int* __restrict__ elen){
    int i = blockIdx.x*blockDim.x + threadIdx.x;
    if (i >= E_TOT) return;
    int l = elen[i]-1;
    unsigned act = __activemask();
    unsigned mask = __match_any_sync(act, l);
    int lane = threadIdx.x & 31, leader = __ffs(mask)-1;
    int rank = __popc(mask & ((1u<<lane)-1));
    int base = 0;
    if (lane == leader) base = atomicAdd(&g_cur[l], __popc(mask));
    base = __shfl_sync(mask, base, leader);
    g_list[base+rank] = i;
}

// ---- x fill: edge e (== tid), step t, into AX[buf] ----
__device__ __forceinline__ void fill_x(char* smem, uint32_t axbase, const float* sTv,
    const float* __restrict__ ef, const float* __restrict__ et, int eg, int t, int e)
{
    float x[16];
    const float4* p = (const float4*)(ef + ((size_t)eg*T + t)*8);
    float4 v0 = __ldg(p), v1 = __ldg(p+1);
    x[0]=v0.x;x[1]=v0.y;x[2]=v0.z;x[3]=v0.w;x[4]=v1.x;x[5]=v1.y;x[6]=v1.z;x[7]=v1.w;
    float tau = __ldg(et + (size_t)eg*T + t);
    #pragma unroll
    for (int k = 0; k < 7; k++) x[8+k] = __sinf(fmaf(tau, sTv[k], sTv[7+k]));
    x[15] = fmaf(tau, sTv[14], sTv[15]);
    #pragma unroll
    for (int u = 0; u < 16; u += 2){
        float ha, hbv;
        uint32_t hi2 = pack_bf2(x[u], x[u+1], ha, hbv);
        __nv_bfloat162 lo; lo.x = __float2bfloat16(x[u]-ha); lo.y = __float2bfloat16(x[u+1]-hbv);
        *(uint32_t*)(smem + sw_el(axbase, e, u))      = hi2;
        *(uint32_t*)(smem + sw_el(axbase, e, 16 + u)) = hi2;
        *(uint32_t*)(smem + sw_el(axbase, e, 32 + u)) = *(uint32_t*)&lo;
    }
}

// ---- LSTM via mma.sync bf16 split; 2 n-halves per warp, 1 sync/step ----
__global__ void __launch_bounds__(512, 1) lstm_hmma_kernel(
    const float* __restrict__ ef, const float* __restrict__ et,
    const int*   __restrict__ elen,
    const float* __restrict__ t2v_w,  const float* __restrict__ t2v_b,
    const float* __restrict__ t2v_w0, const float* __restrict__ t2v_b0,
    const float* __restrict__ Wih_e, const float* __restrict__ Whh_e,
    const float* __restrict__ bih_e, const float* __restrict__ bhh_e,
    const float* __restrict__ Wih_a, const float* __restrict__ Whh_a,
    const float* __restrict__ bih_a, const float* __restrict__ bhh_a)
{
    extern __shared__ char smem[];
    const uint32_t sb = smem_u32(smem);
    int*   sidx = (int*)(smem + OFF_SIDX);
    int*   slen = (int*)(smem + OFF_SLEN);
    float* sTv  = (float*)(smem + OFF_TV);
    int*   smax = (int*)(smem + OFF_SMAX);

    const int tid = threadIdx.x, wid = tid >> 5, lane = tid & 31;
    const bool isA = (blockIdx.y != 0);
    const float* Wih = isA ? Wih_a : Wih_e;
    const float* Whh = isA ? Whh_a : Whh_e;
    const float* bih = isA ? bih_a : bih_e;
    const float* bhh = isA ? bhh_a : bhh_e;
    float* gout = isA ? g_aout : g_eout;

    if (tid == 0) *smax = 0;
    if (tid < 16){
        float v;
        if (tid < 7) v = t2v_w[tid]; else if (tid < 14) v = t2v_b[tid-7];
        else if (tid == 14) v = t2v_w0[0]; else v = t2v_b0[0];
        sTv[tid] = v;
    }
    if (tid < TILE){
        int eg = g_list[blockIdx.x*TILE + tid];
        sidx[tid] = eg;
        int l = elen[eg];
        slen[tid] = l;
        atomicMax(smax, l);
    }
    // zero AHI[0]+ALO... regions that are read-before-written: AHI0/ALO0 + AX both
    {
        float4 z = make_float4(0.f,0.f,0.f,0.f);
        float4* pa = (float4*)(smem + OFF_AHI);
        for (int i = tid; i < 16384/16; i += 512) pa[i] = z;                 // AHI buf0
        float4* pb = (float4*)(smem + OFF_ALO);
        for (int i = tid; i < 16384/16; i += 512) pb[i] = z;                 // ALO buf0
        float4* pc = (float4*)(smem + OFF_AX);
        for (int i = tid; i < 32768/16; i += 512) pc[i] = z;                 // AX both
    }
    // B fill: j = n row (unit-major gate layout: gate = j&3, unit = j>>2)
    {
        int j = tid >> 1, half = tid & 1;
        int srcj = (j & 3)*64 + (j >> 2);
        const float* whr = Whh + srcj*64;
        for (int k = half*32; k < half*32 + 32; k++){
            float w = __ldg(whr + k);
            __nv_bfloat16 hb = __float2bfloat16(w);
            __nv_bfloat16 lb = __float2bfloat16(w - __bfloat162float(hb));
            *(__nv_bfloat16*)(smem + sw_el(OFF_B0, j, k)) = hb;
            *(__nv_bfloat16*)(smem + sw_el(OFF_B1, j, k)) = lb;
        }
        const float* wir = Wih + srcj*16;
        if (half == 0){
            for (int kk = 0; kk < 16; kk++){
                float w = __ldg(wir + kk);
                __nv_bfloat16 hb = __float2bfloat16(w);
                __nv_bfloat16 lb = __float2bfloat16(w - __bfloat162float(hb));
                *(__nv_bfloat16*)(smem + sw_el(OFF_B2, j, kk))      = hb;
                *(__nv_bfloat16*)(smem + sw_el(OFF_B2, j, 16 + kk)) = lb;
            }
        } else {
            for (int kk = 0; kk < 16; kk++)
                *(__nv_bfloat16*)(smem + sw_el(OFF_B2, j, 32 + kk)) = __float2bfloat16(__ldg(wir + kk));
            float bv = __ldg(bih + srcj) + __ldg(bhh + srcj);
            __nv_bfloat16 bh = __float2bfloat16(bv);
            __nv_bfloat16 bl = __float2bfloat16(bv - __bfloat162float(bh));
            *(__nv_bfloat16*)(smem + sw_el(OFF_B2, j, 48)) = bh;
            *(__nv_bfloat16*)(smem + sw_el(OFF_B2, j, 49)) = bl;
            for (int kk = 50; kk < 64; kk++)
                *(__nv_bfloat16*)(smem + sw_el(OFF_B2, j, kk)) = __float2bfloat16(0.f);
        }
    }
    __syncthreads();

    const int maxlen = *smax;
    // ones at k48,49 in BOTH AX buffers + x(0) into AX buf0
    if (tid < TILE){
        __nv_bfloat162 one2; one2.x = __float2bfloat16(1.f); one2.y = one2.x;
        *(uint32_t*)(smem + sw_el(OFF_AX,         tid, 48)) = *(uint32_t*)&one2;
        *(uint32_t*)(smem + sw_el(OFF_AX + 16384, tid, 48)) = *(uint32_t*)&one2;
        fill_x(smem, OFF_AX, sTv, ef, et, sidx[tid], 0, tid);
    }
    __syncthreads();

    // roles
    const int eg = wid >> 1, nh = wid & 1;
    const int ebase = eg*16;
    const int myedge = ebase + (lane >> 2) + ((lane & 1) ? 8 : 0);
    const int myeg_g = sidx[myedge];
    const int mylen  = slen[myedge];
    const int ubit = (lane >> 1) & 1;
    const int pedge = (tid < TILE) ? sidx[tid] : 0;

    float cst[16];
    #pragma unroll
    for (int i = 0; i < 16; i++) cst[i] = 0.f;

    for (int t = 0; t < maxlen; ++t){
        const int par = t & 1;
        const uint32_t aHiR = OFF_AHI + par*16384;
        const uint32_t aLoR = OFF_ALO + par*16384;
        const uint32_t aXR  = OFF_AX  + par*16384;
        const uint32_t aHiW = OFF_AHI + (par^1)*16384;
        const uint32_t aLoW = OFF_ALO + (par^1)*16384;

        // fill x(t+1) into AX[par^1] early (gmem latency overlaps GEMM)
        if (tid < TILE && (t+1) < maxlen)
            fill_x(smem, OFF_AX + (par^1)*16384, sTv, ef, et, pedge, t+1, tid);

        const bool last = (t == mylen - 1);

        #pragma unroll
        for (int half = 0; half < 2; half++){
            const int j0 = nh*128 + half*64;
            float acc[32];
            #pragma unroll
            for (int i = 0; i < 32; i++) acc[i] = 0.f;

            // seg0+1: A = h_hi, B = Whh_hi then Whh_lo
            #pragma unroll
            for (int ks = 0; ks < 4; ks++){
                uint32_t a0,a1,a2,a3;
                { int r = ebase + (lane & 15); int cc = 2*ks + (lane >> 4);
                  ldm4(sw_mat(sb + aHiR, r, cc), a0,a1,a2,a3); }
                int rowb = j0 + ((lane >> 4) << 3) + (lane & 7);
                int chb  = 2*ks + ((lane >> 3) & 1);
                #pragma unroll
                for (int p = 0; p < 4; p++){
                    uint32_t b0,b1,b2,b3;
                    ldm4(sw_mat(sb + OFF_B0, rowb + p*16, chb), b0,b1,b2,b3);
                    mma_bf(&acc[8*p],   a0,a1,a2,a3, b0,b1);
                    mma_bf(&acc[8*p+4], a0,a1,a2,a3, b2,b3);
                }
                #pragma unroll
                for (int p = 0; p < 4; p++){
                    uint32_t b0,b1,b2,b3;
                    ldm4(sw_mat(sb + OFF_B1, rowb + p*16, chb), b0,b1,b2,b3);
                    mma_bf(&acc[8*p],   a0,a1,a2,a3, b0,b1);
                    mma_bf(&acc[8*p+4], a0,a1,a2,a3, b2,b3);
                }
            }
            // seg2: A = h_lo, B = Whh_hi
            #pragma unroll
            for (int ks = 0; ks < 4; ks++){
                uint32_t a0,a1,a2,a3;
                { int r = ebase + (lane & 15); int cc = 2*ks + (lane >> 4);
                  ldm4(sw_mat(sb + aLoR, r, cc), a0,a1,a2,a3); }
                int rowb = j0 + ((lane >> 4) << 3) + (lane & 7);
                int chb  = 2*ks + ((lane >> 3) & 1);
                #pragma unroll
                for (int p = 0; p < 4; p++){
                    uint32_t b0,b1,b2,b3;
                    ldm4(sw_mat(sb + OFF_B0, rowb + p*16, chb), b0,b1,b2,b3);
                    mma_bf(&acc[8*p],   a0,a1,a2,a3, b0,b1);
                    mma_bf(&acc[8*p+4], a0,a1,a2,a3, b2,b3);
                }
            }
            // seg3: A = x combo, B = B2
            #pragma unroll
            for (int ks = 0; ks < 4; ks++){
                uint32_t a0,a1,a2,a3;
                { int r = ebase + (lane & 15); int cc = 2*ks + (lane >> 4);
                  ldm4(sw_mat(sb + aXR, r, cc), a0,a1,a2,a3); }
                int rowb = j0 + ((lane >> 4) << 3) + (lane & 7);
                int chb  = 2*ks + ((lane >> 3) & 1);
                #pragma unroll
                for (int p = 0; p < 4; p++){
                    uint32_t b0,b1,b2,b3;
                    ldm4(sw_mat(sb + OFF_B2, rowb + p*16, chb), b0,b1,b2,b3);
                    mma_bf(&acc[8*p],   a0,a1,a2,a3, b0,b1);
                    mma_bf(&acc[8*p+4], a0,a1,a2,a3, b2,b3);
                }
            }

            // cell update for this half's 16 units (8 n8-tiles)
            #pragma unroll
            for (int tl = 0; tl < 8; tl++){
                float d0 = acc[4*tl], d1 = acc[4*tl+1], d2 = acc[4*tl+2], d3 = acc[4*tl+3];
                float sx = (lane & 1) ? d0 : d2;
                float sy = (lane & 1) ? d1 : d3;
                float rx = __shfl_xor_sync(0xffffffffu, sx, 1);
                float ry = __shfl_xor_sync(0xffffffffu, sy, 1);
                float gi, gf, gg, go;
                if (lane & 1){ gi = rx; gf = ry; gg = d2; go = d3; }
                else         { gi = d0; gf = d1; gg = rx; go = ry; }
                float iv = sigf(gi), fv = sigf(gf), gv = thf(gg), ov = sigf(go);
                int ci = half*8 + tl;
                float cn = fmaf(fv, cst[ci], iv*gv);
                cst[ci] = cn;
                float h = ov * thf(cn);
                int u = nh*32 + half*16 + 2*tl + ubit;
                __nv_bfloat16 hb = __float2bfloat16(h);
                *(__nv_bfloat16*)(smem + sw_el(aHiW, myedge, u)) = hb;
                *(__nv_bfloat16*)(smem + sw_el(aLoW, myedge, u)) = __float2bfloat16(h - __bfloat162float(hb));
                if (last) gout[(size_t)myeg_g*H + u] = h;
            }
        }
        __syncthreads();   // h(t+1), x(t+1) buffers ready for next step
    }
}

// ---- projections: P = nf@eW1^T, Q = nf[:8192]@nW1^T ----
__global__ void proj_kernel(const float* __restrict__ nf,
                            const float* __restrict__ eW, const float* __restrict__ nW)
{
    __shared__ float Wt[64*64];
    __shared__ float xs[16*64];
    const float* W = blockIdx.y ? nW : eW;
    float* out = blockIdx.y ? g_Q : g_P;
    int nrows = blockIdx.y ? N_DST : N_SRC;
    int r0 = blockIdx.x*16;
    if (r0 >= nrows) return;
    int tid = threadIdx.x;
    for (int idx = tid; idx < 4096; idx += 256){ int d = idx>>6, j = idx&63; Wt[idx] = W[j*128 + d]; }
    for (int idx = tid; idx < 1024; idx += 256) xs[idx] = nf[(size_t)r0*64 + idx];
    __syncthreads();
    for (int o = tid; o < 1024; o += 256){
        int ri = o>>6, j = o&63;
        float s = 0.f;
        #pragma unroll
        for (int d = 0; d < 64; d++) s = fmaf(xs[ri*64+d], Wt[d*64+j], s);
        out[(size_t)(r0+ri)*64 + j] = s;
    }
}

// ---- edge epilogue ----
__global__ void __launch_bounds__(256) edgem_kernel(
    const float* __restrict__ eW, const float* __restrict__ eb,
    const float* __restrict__ attn, const int* __restrict__ esrc)
{
    __shared__ float W2t[64*64];
    __shared__ float eo[64*64];
    __shared__ float att[64], bsh[64];
    int tid = threadIdx.x;
    size_t e0 = (size_t)blockIdx.x*64;
    for (int idx = tid; idx < 4096; idx += 256){ int d = idx>>6, j = idx&63; W2t[idx] = eW[j*128 + 64 + d]; }
    if (tid < 64){ att[tid] = attn[tid]; bsh[tid] = eb[tid]; }
    for (int idx = tid; idx < 4096; idx += 256) eo[idx] = g_eout[e0*64 + idx];
    __syncthreads();
    int tm = tid>>5, tn = tid&31;
    float acc[8][2];
    #pragma unroll
    for (int i = 0; i < 8; i++){ acc[i][0] = bsh[tn*2]; acc[i][1] = bsh[tn*2+1]; }
    #pragma unroll 4
    for (int d = 0; d < 64; d++){
        float2 w = *(const float2*)(W2t + d*64 + tn*2);
        #pragma unroll
        for (int i = 0; i < 8; i++){
            float a = eo[(tm*8+i)*64 + d];
            acc[i][0] = fmaf(a, w.x, acc[i][0]);
            acc[i][1] = fmaf(a, w.y, acc[i][1]);
        }
    }
    #pragma unroll
    for (int i = 0; i < 8; i++){
        size_t e = e0 + tm*8 + i;
        int src = esrc[e];
        float2 pv = *(const float2*)(g_P + (size_t)src*64 + tn*2);
        *(float2*)(g_m + e*64 + tn*2) = make_float2(fmaxf(acc[i][0]+pv.x, 0.f), fmaxf(acc[i][1]+pv.y, 0.f));
    }
    if (tid < 64){
        size_t e = e0 + tid;
        const float4* ar = (const float4*)(g_aout + e*64);
        float s = 0.f;
        #pragma unroll
        for (int d = 0; d < 16; d++){
            float4 v = ar[d];
            s += v.x*att[d*4] + v.y*att[d*4+1] + v.z*att[d*4+2] + v.w*att[d*4+3];
        }
        g_a[e] = (s > 0.f) ? s : 0.01f*s;
    }
}

// ---- per-dst: sparsemax + aggregate + final MLP ----
__global__ void __launch_bounds__(256) dst_kernel(
    const float* __restrict__ nW, const float* __restrict__ nb, float* __restrict__ out)
{
    __shared__ float nW2t[64*64];
    __shared__ float nbs[64];
    __shared__ float hns[8][64];
    int tid = threadIdx.x;
    for (int idx = tid; idx < 4096; idx += 256){ int d = idx>>6, j = idx&63; nW2t[idx] = nW[j*128 + 64 + d]; }
    if (tid < 64) nbs[tid] = nb[tid];
    __syncthreads();
    int w = tid>>5, lane = tid&31;
    int dst = blockIdx.x*8 + w;
    const unsigned FULL = 0xffffffffu;

    float av = g_a[(size_t)dst*KNB + lane];
    float mx = av;
    #pragma unroll
    for (int o = 16; o > 0; o >>= 1) mx = fmaxf(mx, __shfl_xor_sync(FULL, mx, o));
    float z = av - mx;
    float v = z;
    #pragma unroll
    for (int k = 2; k <= 32; k <<= 1){
        #pragma unroll
        for (int j = k>>1; j > 0; j >>= 1){
            float o = __shfl_xor_sync(FULL, v, j);
            bool lower = (lane & j) == 0, asc = (lane & k) != 0;
            v = (lower == asc) ? fminf(v, o) : fmaxf(v, o);
        }
    }
    float cs = v;
    #pragma unroll
    for (int o = 1; o < 32; o <<= 1){
        float t = __shfl_up_sync(FULL, cs, o);
        if (lane >= o) cs += t;
    }
    float r = (float)(lane+1);
    bool gt = (1.f + r*v) > cs;
    float kk = gt ? r : 0.f, sz = gt ? v : 0.f;
    #pragma unroll
    for (int o = 16; o > 0; o >>= 1){
        kk = fmaxf(kk, __shfl_xor_sync(FULL, kk, o));
        sz += __shfl_xor_sync(FULL, sz, o);
    }
    float alpha = fmaxf(z - (sz - 1.f)/kk, 0.f);

    float hn0 = 0.f, hn1 = 0.f;
    #pragma unroll
    for (int k2 = 0; k2 < 32; k2++){
        float al = __shfl_sync(FULL, alpha, k2);
        if (al > 0.f){
            const float2 mv = *(const float2*)(g_m + ((size_t)dst*KNB + k2)*64 + lane*2);
            hn0 = fmaf(al, mv.x, hn0);
            hn1 = fmaf(al, mv.y, hn1);
        }
    }
    hns[w][lane*2] = hn0; hns[w][lane*2+1] = hn1;
    __syncwarp();
    float o0 = nbs[lane*2]   + g_Q[(size_t)dst*64 + lane*2];
    float o1 = nbs[lane*2+1] + g_Q[(size_t)dst*64 + lane*2+1];
    #pragma unroll 8
    for (int d = 0; d < 64; d++){
        float h = hns[w][d];
        float2 wv = *(const float2*)(nW2t + d*64 + lane*2);
        o0 = fmaf(h, wv.x, o0);
        o1 = fmaf(h, wv.y, o1);
    }
    size_t ob = (size_t)dst*64 + lane*2;
    out[ob] = fmaxf(o0, 0.f);
    out[ob+1] = fmaxf(o1, 0.f);
}

// ---- launcher ----
extern "C" void kernel_launch(void* const* d_in, const int* in_sizes, int n_in,
                              void* d_out, int out_size)
{
    int iNF,iEF,iET,iLEN,iSRC,iT2W,iT2B,iT2W0,iT2B0;
    int iEWih,iEWhh,iEBih,iEBhh,iAWih,iAWhh,iABih,iABhh,iATT,iEOW,iEOB,iNW,iNB;
    if (in_sizes[3] == E_TOT){
        iNF=0;iEF=1;iET=2;iLEN=3;iSRC=4;iT2W=5;iT2B=6;iT2W0=7;iT2B0=8;
        iEWih=9;iEWhh=10;iEBih=11;iEBhh=12;iAWih=13;iAWhh=14;iABih=15;iABhh=16;
        iATT=17;iEOW=18;iEOB=19;iNW=20;iNB=21;
    } else {
        iNF=0;iEF=1;iET=2;iT2W=3;iT2B=4;iT2W0=5;iT2B0=6;
        iEWih=7;iEWhh=8;iEBih=9;iEBhh=10;iAWih=11;iAWhh=12;iABih=13;iABhh=14;
        iATT=15;iEOW=16;iEOB=17;iNW=18;iNB=19;iLEN=20;iSRC=21;
    }
    const float* nf   = (const float*)d_in[iNF];
    const float* ef   = (const float*)d_in[iEF];
    const float* et   = (const float*)d_in[iET];
    const int*   elen = (const int*)  d_in[iLEN];
    const int*   esrc = (const int*)  d_in[iSRC];
    float* out = (float*)d_out;

    cudaFuncSetAttribute(lstm_hmma_kernel, cudaFuncAttributeMaxDynamicSharedMemorySize, LSTM_SMEM);

    hist_part_kernel<<<128, 256>>>(elen);
    scan2_kernel<<<1, 256>>>();
    scatter_kernel<<<E_TOT/256, 256>>>(elen);

    lstm_hmma_kernel<<<dim3(E_TOT/TILE, 2), 512, LSTM_SMEM>>>(
        ef, et, elen,
        (const float*)d_in[iT2W], (const float*)d_in[iT2B],
        (const float*)d_in[iT2W0], (const float*)d_in[iT2B0],
        (const float*)d_in[iEWih], (const float*)d_in[iEWhh],
        (const float*)d_in[iEBih], (const float*)d_in[iEBhh],
        (const float*)d_in[iAWih], (const float*)d_in[iAWhh],
        (const float*)d_in[iABih], (const float*)d_in[iABhh]);

    proj_kernel<<<dim3(N_SRC/16, 2), 256>>>(nf, (const float*)d_in[iEOW], (const float*)d_in[iNW]);
    edgem_kernel<<<E_TOT/64, 256>>>((const float*)d_in[iEOW], (const float*)d_in[iEOB],
                                    (const float*)d_in[iATT], esrc);
    dst_kernel<<<N_DST/8, 256>>>((const float*)d_in[iNW], (const float*)d_in[iNB], out);
}

// round 6
// speedup vs baseline: 2.4659x; 1.1752x over previous
#include <cuda_runtime.h>
#include <cuda_bf16.h>
#include <math.h>
#include <stdint.h>

#define N_SRC 16384
#define N_DST 8192
#define KNB 32
#define E_TOT (N_DST*KNB)
#define T 16
#define H 64
#define TILE 128

// ---- scratch ----
__device__ float g_eout[(size_t)E_TOT*H];
__device__ float g_aout[(size_t)E_TOT*H];
__device__ float g_m[(size_t)E_TOT*H];
__device__ float g_a[E_TOT];
__device__ float g_P[N_SRC*H];
__device__ float g_Q[N_DST*H];
__device__ int   g_list[E_TOT];
__device__ int   g_part[128][16];
__device__ int   g_cur[T];

// ---- smem byte map ----
// Prologue (B region, freed after B->regs):  B0 @0 (32K), B1 @32768 (32K), B2 @65536 (32K)
// Loop (A region, aliases B):  AHI0 @0, AHI1 @16384, ALO0 @32768, ALO1 @49152, AX0 @65536, AX1 @81920
#define OFF_B0   0
#define OFF_B1   32768
#define OFF_B2   65536
#define OFF_AHI  0
#define OFF_ALO  32768
#define OFF_AX   65536
#define OFF_SIDX 98304
#define OFF_SLEN 98816
#define OFF_TV   99328
#define OFF_SMAX 99392
#define LSTM_SMEM 99456

__device__ __forceinline__ uint32_t smem_u32(const void* p){
    uint32_t a; asm("{ .reg .u64 t; cvta.to.shared.u64 t, %1; cvt.u32.u64 %0, t; }":"=r"(a):"l"(p)); return a;
}
__device__ __forceinline__ uint32_t sw_mat(uint32_t base, int row, int kch){
    return base + (uint32_t)row*128u + ((uint32_t)((kch ^ (row & 7)) & 7) << 4);
}
__device__ __forceinline__ uint32_t sw_el(uint32_t base, int row, int k){
    return base + (uint32_t)row*128u + ((uint32_t)(((k>>3) ^ (row & 7)) & 7) << 4) + ((uint32_t)(k & 7) << 1);
}
__device__ __forceinline__ void ldm4(uint32_t addr, uint32_t &r0, uint32_t &r1, uint32_t &r2, uint32_t &r3){
    asm volatile("ldmatrix.sync.aligned.m8n8.x4.shared.b16 {%0,%1,%2,%3}, [%4];"
        : "=r"(r0),"=r"(r1),"=r"(r2),"=r"(r3) : "r"(addr));
}
__device__ __forceinline__ void mma_bf(float* c, uint32_t a0,uint32_t a1,uint32_t a2,uint32_t a3,
                                       uint32_t b0, uint32_t b1){
    asm volatile("mma.sync.aligned.m16n8k16.row.col.f32.bf16.bf16.f32 "
        "{%0,%1,%2,%3}, {%4,%5,%6,%7}, {%8,%9}, {%0,%1,%2,%3};"
        : "+f"(c[0]),"+f"(c[1]),"+f"(c[2]),"+f"(c[3])
        : "r"(a0),"r"(a1),"r"(a2),"r"(a3),"r"(b0),"r"(b1));
}
__device__ __forceinline__ float sigf(float x){ return __fdividef(1.f, 1.f + __expf(-x)); }
__device__ __forceinline__ float thf(float x) { return 1.f - 2.f*__fdividef(1.f, 1.f + __expf(2.f*x)); }
__device__ __forceinline__ uint32_t pack_bf2(float a, float b, float &ra, float &rb){
    __nv_bfloat162 v; v.x = __float2bfloat16(a); v.y = __float2bfloat16(b);
    ra = __bfloat162float(v.x); rb = __bfloat162float(v.y);
    return *(uint32_t*)&v;
}

// ---- bucketing ----
__global__ void hist_part_kernel(const int* __restrict__ elen){
    __shared__ int h[T];
    if (threadIdx.x < T) h[threadIdx.x] = 0;
    __syncthreads();
    int base = blockIdx.x * 2048;
    for (int i = threadIdx.x; i < 2048; i += 256) atomicAdd(&h[elen[base + i] - 1], 1);
    __syncthreads();
    if (threadIdx.x < T) g_part[blockIdx.x][threadIdx.x] = h[threadIdx.x];
}
__global__ void scan2_kernel(){
    __shared__ int cnt[T];
    if (threadIdx.x < T){
        int s = 0;
        for (int b = 0; b < 128; b++) s += g_part[b][threadIdx.x];
        cnt[threadIdx.x] = s;
    }
    __syncthreads();
    if (threadIdx.x == 0){
        int off = 0;
        for (int l = T-1; l >= 0; --l){ g_cur[l] = off; off += cnt[l]; }
    }
}
__global__ void scatter_kernel(const int* __restrict__ elen){
    int i = blockIdx.x*blockDim.x + threadIdx.x;
    if (i >= E_TOT) return;
    int l = elen[i]-1;
    unsigned act = __activemask();
    unsigned mask = __match_any_sync(act, l);
    int lane = threadIdx.x & 31, leader = __ffs(mask)-1;
    int rank = __popc(mask & ((1u<<lane)-1));
    int base = 0;
    if (lane == leader) base = atomicAdd(&g_cur[l], __popc(mask));
    base = __shfl_sync(mask, base, leader);
    g_list[base+rank] = i;
}

// ---- x fill: edge e (== tid), step t, into AX[buf]; k0-15 x_hi, k16-31 x_hi, k32-47 x_lo ----
__device__ __forceinline__ void fill_x(char* smem, uint32_t axbase, const float* sTv,
    const float* __restrict__ ef, const float* __restrict__ et, int eg, int t, int e)
{
    float x[16];
    const float4* p = (const float4*)(ef + ((size_t)eg*T + t)*8);
    float4 v0 = __ldg(p), v1 = __ldg(p+1);
    x[0]=v0.x;x[1]=v0.y;x[2]=v0.z;x[3]=v0.w;x[4]=v1.x;x[5]=v1.y;x[6]=v1.z;x[7]=v1.w;
    float tau = __ldg(et + (size_t)eg*T + t);
    #pragma unroll
    for (int k = 0; k < 7; k++) x[8+k] = __sinf(fmaf(tau, sTv[k], sTv[7+k]));
    x[15] = fmaf(tau, sTv[14], sTv[15]);
    #pragma unroll
    for (int u = 0; u < 16; u += 2){
        float ha, hbv;
        uint32_t hi2 = pack_bf2(x[u], x[u+1], ha, hbv);
        __nv_bfloat162 lo; lo.x = __float2bfloat16(x[u]-ha); lo.y = __float2bfloat16(x[u+1]-hbv);
        *(uint32_t*)(smem + sw_el(axbase, e, u))      = hi2;
        *(uint32_t*)(smem + sw_el(axbase, e, 16 + u)) = hi2;
        *(uint32_t*)(smem + sw_el(axbase, e, 32 + u)) = *(uint32_t*)&lo;
    }
}

// ---- LSTM: warp-persistent B (n16/warp), m-loop over 8 tiles ----
__global__ void __launch_bounds__(512, 1) lstm_hmma_kernel(
    const float* __restrict__ ef, const float* __restrict__ et,
    const int*   __restrict__ elen,
    const float* __restrict__ t2v_w,  const float* __restrict__ t2v_b,
    const float* __restrict__ t2v_w0, const float* __restrict__ t2v_b0,
    const float* __restrict__ Wih_e, const float* __restrict__ Whh_e,
    const float* __restrict__ bih_e, const float* __restrict__ bhh_e,
    const float* __restrict__ Wih_a, const float* __restrict__ Whh_a,
    const float* __restrict__ bih_a, const float* __restrict__ bhh_a)
{
    extern __shared__ char smem[];
    const uint32_t sb = smem_u32(smem);
    int*   sidx = (int*)(smem + OFF_SIDX);
    int*   slen = (int*)(smem + OFF_SLEN);
    float* sTv  = (float*)(smem + OFF_TV);
    int*   smax = (int*)(smem + OFF_SMAX);

    const int tid = threadIdx.x, wid = tid >> 5, lane = tid & 31;
    const bool isA = (blockIdx.y != 0);
    const float* Wih = isA ? Wih_a : Wih_e;
    const float* Whh = isA ? Whh_a : Whh_e;
    const float* bih = isA ? bih_a : bih_e;
    const float* bhh = isA ? bhh_a : bhh_e;
    float* gout = isA ? g_aout : g_eout;

    if (tid == 0) *smax = 0;
    if (tid < 16){
        float v;
        if (tid < 7) v = t2v_w[tid]; else if (tid < 14) v = t2v_b[tid-7];
        else if (tid == 14) v = t2v_w0[0]; else v = t2v_b0[0];
        sTv[tid] = v;
    }
    if (tid < TILE){
        int eg = g_list[blockIdx.x*TILE + tid];
        sidx[tid] = eg;
        int l = elen[eg];
        slen[tid] = l;
        atomicMax(smax, l);
    }
    // ---- prologue: B into smem (unit-major rows: gate = j&3, unit = j>>2) ----
    {
        int j = tid >> 1, half = tid & 1;
        int srcj = (j & 3)*64 + (j >> 2);
        const float* whr = Whh + srcj*64;
        for (int k = half*32; k < half*32 + 32; k++){
            float w = __ldg(whr + k);
            __nv_bfloat16 hb = __float2bfloat16(w);
            __nv_bfloat16 lb = __float2bfloat16(w - __bfloat162float(hb));
            *(__nv_bfloat16*)(smem + sw_el(OFF_B0, j, k)) = hb;
            *(__nv_bfloat16*)(smem + sw_el(OFF_B1, j, k)) = lb;
        }
        const float* wir = Wih + srcj*16;
        if (half == 0){
            for (int kk = 0; kk < 16; kk++){
                float w = __ldg(wir + kk);
                __nv_bfloat16 hb = __float2bfloat16(w);
                __nv_bfloat16 lb = __float2bfloat16(w - __bfloat162float(hb));
                *(__nv_bfloat16*)(smem + sw_el(OFF_B2, j, kk))      = hb;
                *(__nv_bfloat16*)(smem + sw_el(OFF_B2, j, 16 + kk)) = lb;
            }
        } else {
            for (int kk = 0; kk < 16; kk++)
                *(__nv_bfloat16*)(smem + sw_el(OFF_B2, j, 32 + kk)) = __float2bfloat16(__ldg(wir + kk));
        }
    }
    __syncthreads();

    // ---- B smem -> registers (per warp: n16 slice = rows wid*16..wid*16+15) ----
    uint32_t B0r[4][4], B1r[4][4], B2r[3][4];
    {
        int rowb = wid*16 + ((lane >> 4) << 3) + (lane & 7);
        #pragma unroll
        for (int ks = 0; ks < 4; ks++){
            int chb = 2*ks + ((lane >> 3) & 1);
            ldm4(sw_mat(sb + OFF_B0, rowb, chb), B0r[ks][0],B0r[ks][1],B0r[ks][2],B0r[ks][3]);
            ldm4(sw_mat(sb + OFF_B1, rowb, chb), B1r[ks][0],B1r[ks][1],B1r[ks][2],B1r[ks][3]);
            if (ks < 3)
                ldm4(sw_mat(sb + OFF_B2, rowb, chb), B2r[ks][0],B2r[ks][1],B2r[ks][2],B2r[ks][3]);
        }
    }
    // bias regs: thread's 4 acc columns: n = wid*16 + {2c, 2c+1, 8+2c, 8+2c+1}, c = lane&3
    float b00, b01, b10, b11;
    {
        int c2 = (lane & 3) * 2;
        int n0 = wid*16 + c2;
        int n1 = n0 + 1;
        int n2 = n0 + 8;
        int n3 = n2 + 1;
        #define BIAS_OF(n) (__ldg(bih + ((n)&3)*64 + ((n)>>2)) + __ldg(bhh + ((n)&3)*64 + ((n)>>2)))
        b00 = BIAS_OF(n0); b01 = BIAS_OF(n1); b10 = BIAS_OF(n2); b11 = BIAS_OF(n3);
        #undef BIAS_OF
    }
    // packed lens (nibbles): per m-tile, this thread's output row rc
    const int rc = (lane >> 2) + ((lane & 1) ? 8 : 0);
    uint32_t lens_pk = 0;
    {
        #pragma unroll
        for (int mt = 0; mt < 8; mt++)
            lens_pk |= (uint32_t)((slen[mt*16 + rc] - 1) & 15) << (4*mt);
    }
    __syncthreads();   // B smem reads complete; safe to overwrite with A region

    // ---- A region init: zero AHI0/ALO0, fill AX0 with x(0) ----
    {
        float4 z = make_float4(0.f,0.f,0.f,0.f);
        float4* pa = (float4*)(smem + OFF_AHI);
        for (int i = tid; i < 16384/16; i += 512) pa[i] = z;
        float4* pb = (float4*)(smem + OFF_ALO);
        for (int i = tid; i < 16384/16; i += 512) pb[i] = z;
    }
    const int pedge = (tid < TILE) ? sidx[tid] : 0;
    if (tid < TILE) fill_x(smem, OFF_AX, sTv, ef, et, pedge, 0, tid);
    __syncthreads();

    const int maxlen = *smax;
    const int ubase = wid*4 + ((lane & 2) >> 1);   // + 2*frag gives the unit

    float cst[16];
    #pragma unroll
    for (int i = 0; i < 16; i++) cst[i] = 0.f;

    for (int t = 0; t < maxlen; ++t){
        const int par = t & 1;
        const uint32_t aHiR = OFF_AHI + par*16384;
        const uint32_t aLoR = OFF_ALO + par*16384;
        const uint32_t aXR  = OFF_AX  + par*16384;
        const uint32_t aHiW = OFF_AHI + (par^1)*16384;
        const uint32_t aLoW = OFF_ALO + (par^1)*16384;

        if (tid < TILE && (t+1) < maxlen)
            fill_x(smem, OFF_AX + (par^1)*16384, sTv, ef, et, pedge, t+1, tid);

        #pragma unroll
        for (int mt = 0; mt < 8; mt++){
            float acc[8] = {b00, b01, b00, b01, b10, b11, b10, b11};
            const int r = mt*16 + (lane & 15);
            #pragma unroll
            for (int ks = 0; ks < 4; ks++){
                const int cc = 2*ks + (lane >> 4);
                uint32_t h0,h1,h2,h3, l0,l1,l2,l3;
                ldm4(sw_mat(sb + aHiR, r, cc), h0,h1,h2,h3);
                ldm4(sw_mat(sb + aLoR, r, cc), l0,l1,l2,l3);
                mma_bf(acc,   h0,h1,h2,h3, B0r[ks][0], B0r[ks][1]);
                mma_bf(acc+4, h0,h1,h2,h3, B0r[ks][2], B0r[ks][3]);
                mma_bf(acc,   h0,h1,h2,h3, B1r[ks][0], B1r[ks][1]);
                mma_bf(acc+4, h0,h1,h2,h3, B1r[ks][2], B1r[ks][3]);
                mma_bf(acc,   l0,l1,l2,l3, B0r[ks][0], B0r[ks][1]);
                mma_bf(acc+4, l0,l1,l2,l3, B0r[ks][2], B0r[ks][3]);
                if (ks < 3){
                    uint32_t x0,x1,x2,x3;
                    ldm4(sw_mat(sb + aXR, r, cc), x0,x1,x2,x3);
                    mma_bf(acc,   x0,x1,x2,x3, B2r[ks][0], B2r[ks][1]);
                    mma_bf(acc+4, x0,x1,x2,x3, B2r[ks][2], B2r[ks][3]);
                }
            }
            const bool last = (t == (int)((lens_pk >> (4*mt)) & 15));
            const int edge = mt*16 + rc;
            #pragma unroll
            for (int f = 0; f < 2; f++){
                float d0 = acc[4*f], d1 = acc[4*f+1], d2 = acc[4*f+2], d3 = acc[4*f+3];
                float sx = (lane & 1) ? d0 : d2;
                float sy = (lane & 1) ? d1 : d3;
                float rx = __shfl_xor_sync(0xffffffffu, sx, 1);
                float ry = __shfl_xor_sync(0xffffffffu, sy, 1);
                float gi, gf, gg, go;
                if (lane & 1){ gi = rx; gf = ry; gg = d2; go = d3; }
                else         { gi = d0; gf = d1; gg = rx; go = ry; }
                float iv = sigf(gi), fv = sigf(gf), gv = thf(gg), ov = sigf(go);
                int ci = mt*2 + f;
                float cn = fmaf(fv, cst[ci], iv*gv);
                cst[ci] = cn;
                float h = ov * thf(cn);
                int u = ubase + 2*f;
                __nv_bfloat16 hb = __float2bfloat16(h);
                *(__nv_bfloat16*)(smem + sw_el(aHiW, edge, u)) = hb;
                *(__nv_bfloat16*)(smem + sw_el(aLoW, edge, u)) = __float2bfloat16(h - __bfloat162float(hb));
                if (last) gout[(size_t)sidx[edge]*H + u] = h;
            }
        }
        __syncthreads();
    }
}

// ---- projections: P = nf@eW1^T, Q = nf[:8192]@nW1^T ----
__global__ void proj_kernel(const float* __restrict__ nf,
                            const float* __restrict__ eW, const float* __restrict__ nW)
{
    __shared__ float Wt[64*64];
    __shared__ float xs[16*64];
    const float* W = blockIdx.y ? nW : eW;
    float* out = blockIdx.y ? g_Q : g_P;
    int nrows = blockIdx.y ? N_DST : N_SRC;
    int r0 = blockIdx.x*16;
    if (r0 >= nrows) return;
    int tid = threadIdx.x;
    for (int idx = tid; idx < 4096; idx += 256){ int d = idx>>6, j = idx&63; Wt[idx] = W[j*128 + d]; }
    for (int idx = tid; idx < 1024; idx += 256) xs[idx] = nf[(size_t)r0*64 + idx];
    __syncthreads();
    for (int o = tid; o < 1024; o += 256){
        int ri = o>>6, j = o&63;
        float s = 0.f;
        #pragma unroll
        for (int d = 0; d < 64; d++) s = fmaf(xs[ri*64+d], Wt[d*64+j], s);
        out[(size_t)(r0+ri)*64 + j] = s;
    }
}

// ---- edge epilogue ----
__global__ void __launch_bounds__(256) edgem_kernel(
    const float* __restrict__ eW, const float* __restrict__ eb,
    const float* __restrict__ attn, const int* __restrict__ esrc)
{
    __shared__ float W2t[64*64];
    __shared__ float eo[64*64];
    __shared__ float att[64], bsh[64];
    int tid = threadIdx.x;
    size_t e0 = (size_t)blockIdx.x*64;
    for (int idx = tid; idx < 4096; idx += 256){ int d = idx>>6, j = idx&63; W2t[idx] = eW[j*128 + 64 + d]; }
    if (tid < 64){ att[tid] = attn[tid]; bsh[tid] = eb[tid]; }
    for (int idx = tid; idx < 4096; idx += 256) eo[idx] = g_eout[e0*64 + idx];
    __syncthreads();
    int tm = tid>>5, tn = tid&31;
    float acc[8][2];
    #pragma unroll
    for (int i = 0; i < 8; i++){ acc[i][0] = bsh[tn*2]; acc[i][1] = bsh[tn*2+1]; }
    #pragma unroll 4
    for (int d = 0; d < 64; d++){
        float2 w = *(const float2*)(W2t + d*64 + tn*2);
        #pragma unroll
        for (int i = 0; i < 8; i++){
            float a = eo[(tm*8+i)*64 + d];
            acc[i][0] = fmaf(a, w.x, acc[i][0]);
            acc[i][1] = fmaf(a, w.y, acc[i][1]);
        }
    }
    #pragma unroll
    for (int i = 0; i < 8; i++){
        size_t e = e0 + tm*8 + i;
        int src = esrc[e];
        float2 pv = *(const float2*)(g_P + (size_t)src*64 + tn*2);
        *(float2*)(g_m + e*64 + tn*2) = make_float2(fmaxf(acc[i][0]+pv.x, 0.f), fmaxf(acc[i][1]+pv.y, 0.f));
    }
    if (tid < 64){
        size_t e = e0 + tid;
        const float4* ar = (const float4*)(g_aout + e*64);
        float s = 0.f;
        #pragma unroll
        for (int d = 0; d < 16; d++){
            float4 v = ar[d];
            s += v.x*att[d*4] + v.y*att[d*4+1] + v.z*att[d*4+2] + v.w*att[d*4+3];
        }
        g_a[e] = (s > 0.f) ? s : 0.01f*s;
    }
}

// ---- per-dst: sparsemax + aggregate + final MLP ----
__global__ void __launch_bounds__(256) dst_kernel(
    const float* __restrict__ nW, const float* __restrict__ nb, float* __restrict__ out)
{
    __shared__ float nW2t[64*64];
    __shared__ float nbs[64];
    __shared__ float hns[8][64];
    int tid = threadIdx.x;
    for (int idx = tid; idx < 4096; idx += 256){ int d = idx>>6, j = idx&63; nW2t[idx] = nW[j*128 + 64 + d]; }
    if (tid < 64) nbs[tid] = nb[tid];
    __syncthreads();
    int w = tid>>5, lane = tid&31;
    int dst = blockIdx.x*8 + w;
    const unsigned FULL = 0xffffffffu;

    float av = g_a[(size_t)dst*KNB + lane];
    float mx = av;
    #pragma unroll
    for (int o = 16; o > 0; o >>= 1) mx = fmaxf(mx, __shfl_xor_sync(FULL, mx, o));
    float z = av - mx;
    float v = z;
    #pragma unroll
    for (int k = 2; k <= 32; k <<= 1){
        #pragma unroll
        for (int j = k>>1; j > 0; j >>= 1){
            float o = __shfl_xor_sync(FULL, v, j);
            bool lower = (lane & j) == 0, asc = (lane & k) != 0;
            v = (lower == asc) ? fminf(v, o) : fmaxf(v, o);
        }
    }
    float cs = v;
    #pragma unroll
    for (int o = 1; o < 32; o <<= 1){
        float t = __shfl_up_sync(FULL, cs, o);
        if (lane >= o) cs += t;
    }
    float r = (float)(lane+1);
    bool gt = (1.f + r*v) > cs;
    float kk = gt ? r : 0.f, sz = gt ? v : 0.f;
    #pragma unroll
    for (int o = 16; o > 0; o >>= 1){
        kk = fmaxf(kk, __shfl_xor_sync(FULL, kk, o));
        sz += __shfl_xor_sync(FULL, sz, o);
    }
    float alpha = fmaxf(z - (sz - 1.f)/kk, 0.f);

    float hn0 = 0.f, hn1 = 0.f;
    #pragma unroll
    for (int k2 = 0; k2 < 32; k2++){
        float al = __shfl_sync(FULL, alpha, k2);
        if (al > 0.f){
            const float2 mv = *(const float2*)(g_m + ((size_t)dst*KNB + k2)*64 + lane*2);
            hn0 = fmaf(al, mv.x, hn0);
            hn1 = fmaf(al, mv.y, hn1);
        }
    }
    hns[w][lane*2] = hn0; hns[w][lane*2+1] = hn1;
    __syncwarp();
    float o0 = nbs[lane*2]   + g_Q[(size_t)dst*64 + lane*2];
    float o1 = nbs[lane*2+1] + g_Q[(size_t)dst*64 + lane*2+1];
    #pragma unroll 8
    for (int d = 0; d < 64; d++){
        float h = hns[w][d];
        float2 wv = *(const float2*)(nW2t + d*64 + lane*2);
        o0 = fmaf(h, wv.x, o0);
        o1 = fmaf(h, wv.y, o1);
    }
    size_t ob = (size_t)dst*64 + lane*2;
    out[ob] = fmaxf(o0, 0.f);
    out[ob+1] = fmaxf(o1, 0.f);
}

// ---- launcher ----
extern "C" void kernel_launch(void* const* d_in, const int* in_sizes, int n_in,
                              void* d_out, int out_size)
{
    int iNF,iEF,iET,iLEN,iSRC,iT2W,iT2B,iT2W0,iT2B0;
    int iEWih,iEWhh,iEBih,iEBhh,iAWih,iAWhh,iABih,iABhh,iATT,iEOW,iEOB,iNW,iNB;
    if (in_sizes[3] == E_TOT){
        iNF=0;iEF=1;iET=2;iLEN=3;iSRC=4;iT2W=5;iT2B=6;iT2W0=7;iT2B0=8;
        iEWih=9;iEWhh=10;iEBih=11;iEBhh=12;iAWih=13;iAWhh=14;iABih=15;iABhh=16;
        iATT=17;iEOW=18;iEOB=19;iNW=20;iNB=21;
    } else {
        iNF=0;iEF=1;iET=2;iT2W=3;iT2B=4;iT2W0=5;iT2B0=6;
        iEWih=7;iEWhh=8;iEBih=9;iEBhh=10;iAWih=11;iAWhh=12;iABih=13;iABhh=14;
        iATT=15;iEOW=16;iEOB=17;iNW=18;iNB=19;iLEN=20;iSRC=21;
    }
    const float* nf   = (const float*)d_in[iNF];
    const float* ef   = (const float*)d_in[iEF];
    const float* et   = (const float*)d_in[iET];
    const int*   elen = (const int*)  d_in[iLEN];
    const int*   esrc = (const int*)  d_in[iSRC];
    float* out = (float*)d_out;

    cudaFuncSetAttribute(lstm_hmma_kernel, cudaFuncAttributeMaxDynamicSharedMemorySize, LSTM_SMEM);

    hist_part_kernel<<<128, 256>>>(elen);
    scan2_kernel<<<1, 256>>>();
    scatter_kernel<<<E_TOT/256, 256>>>(elen);

    lstm_hmma_kernel<<<dim3(E_TOT/TILE, 2), 512, LSTM_SMEM>>>(
        ef, et, elen,
        (const float*)d_in[iT2W], (const float*)d_in[iT2B],
        (const float*)d_in[iT2W0], (const float*)d_in[iT2B0],
        (const float*)d_in[iEWih], (const float*)d_in[iEWhh],
        (const float*)d_in[iEBih], (const float*)d_in[iEBhh],
        (const float*)d_in[iAWih], (const float*)d_in[iAWhh],
        (const float*)d_in[iABih], (const float*)d_in[iABhh]);

    proj_kernel<<<dim3(N_SRC/16, 2), 256>>>(nf, (const float*)d_in[iEOW], (const float*)d_in[iNW]);
    edgem_kernel<<<E_TOT/64, 256>>>((const float*)d_in[iEOW], (const float*)d_in[iEOB],
                                    (const float*)d_in[iATT], esrc);
    dst_kernel<<<N_DST/8, 256>>>((const float*)d_in[iNW], (const float*)d_in[iNB], out);
}